// round 15
// baseline (speedup 1.0000x reference)
#include <cuda_runtime.h>
#include <cuda_bf16.h>
#include <cstdint>

#define BROWS 32768
#define NUM_EXPERTS 10
#define NUM_LEVELS 4
#define CBK 256
#define ZD 128
#define BETA 0.001f
#define RQ_ROWS 32
#define TAU 1e-3f

#define OUT_OFF  0
#define LOSS_OFF (32768 * 768)
#define IDX_OFF  (LOSS_OFF + 1)
#define XQ_OFF   (IDX_OFF + 32768 * 4)

// ---------------------------------------------------------------------------
// Device scratch
// ---------------------------------------------------------------------------
__device__ float g_res [32768 * ZD];
__device__ float g_xq  [32768 * ZD];
__device__ float g_lossbuf[32768];
__device__ int   g_counts[NUM_EXPERTS];
__device__ int   g_cursor[NUM_EXPERTS];
__device__ int   g_offsets[NUM_EXPERTS + 1];
__device__ int   g_perm[32768];
__device__ int   g_rowflag[32768];
__device__ int   g_replist[32768];
__device__ int   g_nrep;

// bf16 hi/lo activation ping-pong (shared by encoder and decoder) + weights
__device__ __nv_bfloat16 g_dA0[32768u * 1024u];
__device__ __nv_bfloat16 g_dA1[32768u * 1024u];
__device__ __nv_bfloat16 g_dB0[32768u * 2048u];
__device__ __nv_bfloat16 g_dB1[32768u * 2048u];
#define W_TOTAL 4259840
__device__ __nv_bfloat16 g_dw0[W_TOTAL];
__device__ __nv_bfloat16 g_dw1[W_TOTAL];
__device__ __nv_bfloat16 g_ew0[W_TOTAL];
__device__ __nv_bfloat16 g_ew1[W_TOTAL];

// ---------------------------------------------------------------------------
// PTX helpers
// ---------------------------------------------------------------------------
__device__ __forceinline__ uint32_t smem_u32(const void* p) {
    uint32_t a;
    asm("{ .reg .u64 t; cvta.to.shared.u64 t, %1; cvt.u32.u64 %0, t; }"
        : "=r"(a) : "l"(p));
    return a;
}
__device__ __forceinline__ void cpa16(uint32_t dst, const void* src) {
    asm volatile("cp.async.cg.shared.global [%0], [%1], 16;" :: "r"(dst), "l"(src) : "memory");
}
#define CP_COMMIT() asm volatile("cp.async.commit_group;" ::: "memory")
#define CP_WAIT(n)  asm volatile("cp.async.wait_group %0;" :: "n"(n) : "memory")

#define LDSM4(r0, r1, r2, r3, addr) \
    asm volatile("ldmatrix.sync.aligned.m8n8.x4.shared.b16 {%0,%1,%2,%3}, [%4];" \
        : "=r"(r0), "=r"(r1), "=r"(r2), "=r"(r3) : "r"(addr))

#define MMA16816(acc, a, b0, b1) \
    asm volatile("mma.sync.aligned.m16n8k16.row.col.f32.bf16.bf16.f32 " \
        "{%0,%1,%2,%3}, {%4,%5,%6,%7}, {%8,%9}, {%0,%1,%2,%3};" \
        : "+f"((acc)[0]), "+f"((acc)[1]), "+f"((acc)[2]), "+f"((acc)[3]) \
        : "r"((a)[0]), "r"((a)[1]), "r"((a)[2]), "r"((a)[3]), "r"(b0), "r"(b1))

// ---------------------------------------------------------------------------
// HMMA bf16x3 GEMM (validated; STAGES=2 -> 2 CTAs/SM). Used for encoder AND
// decoder now. OMODE 0: fp32 C. OMODE 1: bf16 hi/lo split C.
// ---------------------------------------------------------------------------
#define TSTRIDE 40
#define SUBTILE (128 * TSTRIDE * 2)

template <int STAGES, bool RELU, int OMODE>
__global__ __launch_bounds__(256)
void hmma_gemm(const __nv_bfloat16* __restrict__ A0, const __nv_bfloat16* __restrict__ A1,
               const __nv_bfloat16* __restrict__ B0, const __nv_bfloat16* __restrict__ B1,
               const float* __restrict__ bias, float* __restrict__ Cf,
               __nv_bfloat16* __restrict__ C0, __nv_bfloat16* __restrict__ C1,
               int M, int N, int K)
{
    constexpr int STAGE = 4 * SUBTILE;
    extern __shared__ char smem[];
    const uint32_t sbase = smem_u32(smem);

    const int tid  = threadIdx.x;
    const int lane = tid & 31;
    const int wid  = tid >> 5;
    const int wm   = wid & 3;
    const int wn   = wid >> 2;
    const int m0   = blockIdx.y * 128;
    const int n0   = blockIdx.x * 128;
    const int nch  = K >> 5;

    float acc[2][8][4];
#pragma unroll
    for (int a = 0; a < 2; a++)
#pragma unroll
        for (int b = 0; b < 8; b++)
#pragma unroll
            for (int c = 0; c < 4; c++) acc[a][b][c] = 0.f;

    auto load_stage = [&](int stg, int k0) {
        const uint32_t sb_ = sbase + stg * STAGE;
#pragma unroll
        for (int ii = 0; ii < 2; ii++) {
            const int i = tid + ii * 256;
            const int r = i >> 2, c = i & 3;
            const uint32_t so = r * 80 + c * 16;
            const size_t ga = (size_t)(m0 + r) * K + k0 + c * 8;
            const size_t gb = (size_t)(n0 + r) * K + k0 + c * 8;
            cpa16(sb_ + so,               A0 + ga);
            cpa16(sb_ + SUBTILE + so,     A1 + ga);
            cpa16(sb_ + 2 * SUBTILE + so, B0 + gb);
            cpa16(sb_ + 3 * SUBTILE + so, B1 + gb);
        }
    };

#pragma unroll
    for (int s = 0; s < STAGES; s++) {
        if (s < nch) load_stage(s, s * 32);
        CP_COMMIT();
    }

    const int lrow = lane & 15;
    const int lsel = (lane >> 4) << 3;

    for (int ch = 0; ch < nch; ch++) {
        CP_WAIT(STAGES - 1);
        __syncthreads();
        const uint32_t sb = sbase + (ch % STAGES) * STAGE;
        const uint32_t Ahb = sb, Alb = sb + SUBTILE;
        const uint32_t Bhb = sb + 2 * SUBTILE, Blb = sb + 3 * SUBTILE;

#pragma unroll
        for (int kk = 0; kk < 32; kk += 16) {
            uint32_t ah[2][4], al[2][4];
#pragma unroll
            for (int mt = 0; mt < 2; mt++) {
                uint32_t off = ((wm * 32 + mt * 16 + lrow) * TSTRIDE + kk + lsel) * 2;
                LDSM4(ah[mt][0], ah[mt][1], ah[mt][2], ah[mt][3], Ahb + off);
                LDSM4(al[mt][0], al[mt][1], al[mt][2], al[mt][3], Alb + off);
            }
            uint32_t bh[8][2], bl[8][2];
#pragma unroll
            for (int g = 0; g < 4; g++) {
                uint32_t off = ((wn * 64 + g * 16 + lrow) * TSTRIDE + kk + lsel) * 2;
                uint32_t t0, t1, t2, t3;
                LDSM4(t0, t1, t2, t3, Bhb + off);
                bh[2*g][0] = t0;   bh[2*g][1] = t2;
                bh[2*g+1][0] = t1; bh[2*g+1][1] = t3;
                LDSM4(t0, t1, t2, t3, Blb + off);
                bl[2*g][0] = t0;   bl[2*g][1] = t2;
                bl[2*g+1][0] = t1; bl[2*g+1][1] = t3;
            }
#pragma unroll
            for (int mt = 0; mt < 2; mt++)
#pragma unroll
                for (int nt = 0; nt < 8; nt++) {
                    MMA16816(acc[mt][nt], ah[mt], bh[nt][0], bh[nt][1]);
                    MMA16816(acc[mt][nt], ah[mt], bl[nt][0], bl[nt][1]);
                    MMA16816(acc[mt][nt], al[mt], bh[nt][0], bh[nt][1]);
                }
        }
        __syncthreads();
        if (ch + STAGES < nch) load_stage(ch % STAGES, (ch + STAGES) * 32);
        CP_COMMIT();
    }

    const int gid = lane >> 2;
    const int tg  = lane & 3;
#pragma unroll
    for (int mt = 0; mt < 2; mt++) {
#pragma unroll
        for (int nt = 0; nt < 8; nt++) {
            const int col = n0 + wn * 64 + nt * 8 + tg * 2;
            const float2 bb = __ldg((const float2*)(bias + col));
#pragma unroll
            for (int h = 0; h < 2; h++) {
                const int row = m0 + wm * 32 + mt * 16 + gid + h * 8;
                float v0 = acc[mt][nt][2*h]   + bb.x;
                float v1 = acc[mt][nt][2*h+1] + bb.y;
                if (RELU) { v0 = fmaxf(v0, 0.f); v1 = fmaxf(v1, 0.f); }
                if (OMODE == 0) {
                    *(float2*)(Cf + (size_t)row * N + col) = make_float2(v0, v1);
                } else {
                    __nv_bfloat16 h0 = __float2bfloat16(v0);
                    __nv_bfloat16 h1 = __float2bfloat16(v1);
                    __nv_bfloat162 p0; p0.x = h0; p0.y = h1;
                    __nv_bfloat162 p1;
                    p1.x = __float2bfloat16(v0 - __bfloat162float(h0));
                    p1.y = __float2bfloat16(v1 - __bfloat162float(h1));
                    *(__nv_bfloat162*)(C0 + (size_t)row * N + col) = p0;
                    *(__nv_bfloat162*)(C1 + (size_t)row * N + col) = p1;
                }
            }
        }
    }
}

// ---------------------------------------------------------------------------
// Preprocessing
// ---------------------------------------------------------------------------
__global__ void k_wprep2(const float* __restrict__ W, __nv_bfloat16* __restrict__ T0,
                         __nv_bfloat16* __restrict__ T1, int K, int N)
{
    __shared__ float t[32][33];
    int n = blockIdx.x * 32 + threadIdx.x;
    int k = blockIdx.y * 32 + threadIdx.y;
    t[threadIdx.y][threadIdx.x] = W[(size_t)k * N + n];
    __syncthreads();
    int nn = blockIdx.x * 32 + threadIdx.y;
    int kk = blockIdx.y * 32 + threadIdx.x;
    float v = t[threadIdx.x][threadIdx.y];
    __nv_bfloat16 h = __float2bfloat16(v);
    T0[(size_t)nn * K + kk] = h;
    T1[(size_t)nn * K + kk] = __float2bfloat16(v - __bfloat162float(h));
}

__global__ void k_split(const float* __restrict__ src, __nv_bfloat16* __restrict__ o0,
                        __nv_bfloat16* __restrict__ o1, int n)
{
    int i = blockIdx.x * 256 + threadIdx.x;
    if (i < n) {
        float v = src[i];
        __nv_bfloat16 h = __float2bfloat16(v);
        o0[i] = h;
        o1[i] = __float2bfloat16(v - __bfloat162float(h));
    }
}

__global__ void k_xq_out(const float* __restrict__ xq, float* __restrict__ dst,
                         __nv_bfloat16* __restrict__ o0, __nv_bfloat16* __restrict__ o1)
{
    int i = blockIdx.x * 256 + threadIdx.x;
    if (i < BROWS * ZD) {
        float v = xq[i];
        dst[i] = v;
        __nv_bfloat16 h = __float2bfloat16(v);
        o0[i] = h;
        o1[i] = __float2bfloat16(v - __bfloat162float(h));
    }
}

// ---------------------------------------------------------------------------
// Expert counting-sort + init
// ---------------------------------------------------------------------------
__global__ void k_zero_counts() {
    int t = threadIdx.x;
    if (t < NUM_EXPERTS) { g_counts[t] = 0; g_cursor[t] = 0; }
    if (t == 0) g_nrep = 0;
}
__global__ void k_hist(const int* __restrict__ labels) {
    int i = blockIdx.x * blockDim.x + threadIdx.x;
    if (i < BROWS) atomicAdd(&g_counts[labels[i]], 1);
}
__global__ void k_scan() {
    if (threadIdx.x == 0) {
        int s = 0;
        for (int e = 0; e < NUM_EXPERTS; e++) { g_offsets[e] = s; s += g_counts[e]; }
        g_offsets[NUM_EXPERTS] = s;
    }
}
__global__ void k_scatter(const int* __restrict__ labels) {
    int i = blockIdx.x * blockDim.x + threadIdx.x;
    if (i < BROWS) {
        int e = labels[i];
        int p = atomicAdd(&g_cursor[e], 1);
        g_perm[g_offsets[e] + p] = i;
    }
}
__global__ void k_rq_init() {
    int i = blockIdx.x * blockDim.x + threadIdx.x;
    if (i < BROWS * ZD) g_xq[i] = 0.f;
    if (i < BROWS) { g_lossbuf[i] = 0.f; g_rowflag[i] = 0; }
}

// ---------------------------------------------------------------------------
// Residual quantization with top-2 margin flagging.
// Selection math identical to the validated kernel; additionally tracks the
// second-best score and flags rows whose gap is within TAU of the scale.
// ---------------------------------------------------------------------------
__global__ void rq_level(const float* __restrict__ cb,
                         float* __restrict__ idx_out, int level)
{
    extern __shared__ float c_sh[];        // 256 * 129 floats
    __shared__ float res_sh[ZD];
    __shared__ float cn_sh[CBK];
    __shared__ float s_ws[8];
    __shared__ int   s_wi[8];
    __shared__ float s_w2[8];
    __shared__ float s_red[4];
    __shared__ int   s_kmin;

    const int e     = blockIdx.y;
    const int start = g_offsets[e];
    const int end   = g_offsets[e + 1];
    const int rbase = start + blockIdx.x * RQ_ROWS;
    if (rbase >= end) return;

    const int t = threadIdx.x;
    const int lane = t & 31;
    const int warp = t >> 5;
    const float INF = __int_as_float(0x7f800000);

    const float* cbl = cb + ((size_t)level * NUM_EXPERTS + e) * CBK * ZD;
    for (int i = t; i < (CBK * ZD) / 4; i += 256) {
        float4 v = ((const float4*)cbl)[i];
        int k = i >> 5;
        int j = (i & 31) << 2;
        float* d = &c_sh[k * 129 + j];
        d[0] = v.x; d[1] = v.y; d[2] = v.z; d[3] = v.w;
    }
    __syncthreads();

    {
        const float* cr = &c_sh[t * 129];
        float s = 0.f;
#pragma unroll 8
        for (int j = 0; j < ZD; j++) s += cr[j] * cr[j];
        cn_sh[t] = s;
    }
    __syncthreads();

    const int nrows = min(RQ_ROWS, end - rbase);
    for (int i = 0; i < nrows; i++) {
        const int row = g_perm[rbase + i];
        if (t < ZD) res_sh[t] = g_res[row * ZD + t];
        __syncthreads();

        float dot = 0.f;
        const float* cr = &c_sh[t * 129];
#pragma unroll 8
        for (int j = 0; j < ZD; j++) dot += cr[j] * res_sh[j];
        float s1 = cn_sh[t] - 2.f * dot;
        int   i1 = t;
        float s2 = INF;

        // warp lexicographic top-2 (min + runner-up value)
#pragma unroll
        for (int o = 16; o > 0; o >>= 1) {
            float t1 = __shfl_down_sync(0xffffffffu, s1, o);
            int   j1 = __shfl_down_sync(0xffffffffu, i1, o);
            float t2 = __shfl_down_sync(0xffffffffu, s2, o);
            if (t1 < s1 || (t1 == s1 && j1 < i1)) {
                s2 = fminf(s1, t2);
                s1 = t1; i1 = j1;
            } else {
                s2 = fminf(s2, t1);
            }
        }
        if (lane == 0) { s_ws[warp] = s1; s_wi[warp] = i1; s_w2[warp] = s2; }
        __syncthreads();
        if (t == 0) {
            float bs = s_ws[0]; int bi = s_wi[0]; float b2 = s_w2[0];
#pragma unroll
            for (int w = 1; w < 8; w++) {
                float u1 = s_ws[w]; int u = s_wi[w]; float u2 = s_w2[w];
                if (u1 < bs || (u1 == bs && u < bi)) {
                    b2 = fminf(bs, u2);
                    bs = u1; bi = u;
                } else {
                    b2 = fminf(b2, u1);
                }
            }
            s_kmin = bi;
            if (b2 - bs < TAU * (1.0f + fabsf(bs))) g_rowflag[row] = 1;
        }
        __syncthreads();
        const int kmin = s_kmin;

        float sq = 0.f;
        if (t < ZD) {
            float q  = c_sh[kmin * 129 + t];
            float nr = res_sh[t] - q;
            g_res[row * ZD + t] = nr;
            g_xq [row * ZD + t] += q;
            sq = nr * nr;
        }
#pragma unroll
        for (int o = 16; o > 0; o >>= 1) sq += __shfl_down_sync(0xffffffffu, sq, o);
        if (t < ZD && lane == 0) s_red[warp] = sq;
        __syncthreads();
        if (t == 0) {
            g_lossbuf[row] += s_red[0] + s_red[1] + s_red[2] + s_red[3];
            idx_out[row * 4 + level] = (float)kmin;
        }
        __syncthreads();
    }
}

__global__ void k_compact() {
    int i = blockIdx.x * blockDim.x + threadIdx.x;
    if (i < BROWS && g_rowflag[i]) {
        int p = atomicAdd(&g_nrep, 1);
        g_replist[p] = i;
    }
}

// ---------------------------------------------------------------------------
// Exact repair: flagged rows recompute z with bitwise-fp32 (serial ascending-k
// FMA per element — identical chain to any exact SGEMM) and redo all 4 RQ
// levels with the identical expressions, overwriting idx/x_q/loss.
// ---------------------------------------------------------------------------
__global__ __launch_bounds__(256)
void k_repair(const float* __restrict__ x, const int* __restrict__ labels,
              const float* __restrict__ w0, const float* __restrict__ b0,
              const float* __restrict__ w1, const float* __restrict__ b1,
              const float* __restrict__ w2, const float* __restrict__ b2,
              const float* __restrict__ w3, const float* __restrict__ b3,
              const float* __restrict__ cb, float* __restrict__ idx_out)
{
    __shared__ float hA[2048];
    __shared__ float hB[2048];
    __shared__ float res_s[ZD];
    __shared__ float xq_s[ZD];
    __shared__ float s_ws[8];
    __shared__ int   s_wi[8];
    __shared__ float s_red[4];
    __shared__ int   s_kmin;
    __shared__ float s_loss;

    const int t = threadIdx.x;
    const int lane = t & 31;
    const int warp = t >> 5;

    for (int fi = blockIdx.x; fi < g_nrep; fi += gridDim.x) {
        const int row = g_replist[fi];

        // load x row
        for (int j = t; j < 768; j += 256) hA[j] = x[(size_t)row * 768 + j];
        __syncthreads();

        // L0: 768 -> 2048, relu
        for (int j = t; j < 2048; j += 256) {
            float acc = 0.f;
            for (int k = 0; k < 768; k++) acc = fmaf(hA[k], w0[(size_t)k * 2048 + j], acc);
            hB[j] = fmaxf(acc + b0[j], 0.f);
        }
        __syncthreads();
        // L1: 2048 -> 1024, relu
        for (int j = t; j < 1024; j += 256) {
            float acc = 0.f;
            for (int k = 0; k < 2048; k++) acc = fmaf(hB[k], w1[(size_t)k * 1024 + j], acc);
            hA[j] = fmaxf(acc + b1[j], 0.f);
        }
        __syncthreads();
        // L2: 1024 -> 512, relu
        for (int j = t; j < 512; j += 256) {
            float acc = 0.f;
            for (int k = 0; k < 1024; k++) acc = fmaf(hA[k], w2[(size_t)k * 512 + j], acc);
            hB[j] = fmaxf(acc + b2[j], 0.f);
        }
        __syncthreads();
        // L3: 512 -> 128, no relu (z)
        if (t < ZD) {
            float acc = 0.f;
            for (int k = 0; k < 512; k++) acc = fmaf(hB[k], w3[(size_t)k * 128 + t], acc);
            res_s[t] = acc + b3[t];
            xq_s[t] = 0.f;
        }
        if (t == 0) s_loss = 0.f;
        __syncthreads();

        const int e = labels[row];
        for (int l = 0; l < NUM_LEVELS; l++) {
            const float* cbl = cb + ((size_t)l * NUM_EXPERTS + e) * CBK * ZD;
            const float* cr = cbl + (size_t)t * ZD;
            float cn = 0.f, dot = 0.f;
            for (int j = 0; j < ZD; j++) cn  += cr[j] * cr[j];
            for (int j = 0; j < ZD; j++) dot += cr[j] * res_s[j];
            float sc = cn - 2.f * dot;
            int   ix = t;
#pragma unroll
            for (int o = 16; o > 0; o >>= 1) {
                float sc2 = __shfl_down_sync(0xffffffffu, sc, o);
                int   ix2 = __shfl_down_sync(0xffffffffu, ix, o);
                if (sc2 < sc || (sc2 == sc && ix2 < ix)) { sc = sc2; ix = ix2; }
            }
            if (lane == 0) { s_ws[warp] = sc; s_wi[warp] = ix; }
            __syncthreads();
            if (t == 0) {
                float bs = s_ws[0]; int bi = s_wi[0];
#pragma unroll
                for (int w = 1; w < 8; w++) {
                    float u = s_ws[w]; int ui = s_wi[w];
                    if (u < bs || (u == bs && ui < bi)) { bs = u; bi = ui; }
                }
                s_kmin = bi;
            }
            __syncthreads();
            const int kmin = s_kmin;

            float sq = 0.f;
            if (t < ZD) {
                float q  = cbl[(size_t)kmin * ZD + t];
                float nr = res_s[t] - q;
                res_s[t] = nr;
                xq_s[t] += q;
                sq = nr * nr;
            }
            __syncthreads();   // res_s update visible before next level reads
#pragma unroll
            for (int o = 16; o > 0; o >>= 1) sq += __shfl_down_sync(0xffffffffu, sq, o);
            if (t < ZD && lane == 0) s_red[warp] = sq;
            __syncthreads();
            if (t == 0) {
                s_loss += s_red[0] + s_red[1] + s_red[2] + s_red[3];
                idx_out[row * 4 + l] = (float)kmin;
            }
            __syncthreads();
        }
        if (t < ZD) g_xq[(size_t)row * ZD + t] = xq_s[t];
        if (t == 0) g_lossbuf[row] = s_loss;
        __syncthreads();
    }
}

__global__ void k_loss_finish(float* __restrict__ loss_out) {
    __shared__ float sm[1024];
    float s = 0.f;
    for (int i = threadIdx.x; i < BROWS; i += 1024) s += g_lossbuf[i];
    sm[threadIdx.x] = s;
    __syncthreads();
    for (int k = 512; k > 0; k >>= 1) {
        if (threadIdx.x < k) sm[threadIdx.x] += sm[threadIdx.x + k];
        __syncthreads();
    }
    if (threadIdx.x == 0)
        loss_out[0] = sm[0] * (1.f + BETA) / ((float)BROWS * (float)ZD);
}

// ---------------------------------------------------------------------------
// Host launch
// ---------------------------------------------------------------------------
template <int STAGES, bool RELU, int OMODE>
static void launch_hmma(const __nv_bfloat16* a0, const __nv_bfloat16* a1,
                        const __nv_bfloat16* b0, const __nv_bfloat16* b1,
                        const float* bias, float* cf,
                        __nv_bfloat16* c0, __nv_bfloat16* c1,
                        int M, int N, int K)
{
    constexpr int SMEMB = STAGES * 4 * SUBTILE;
    cudaFuncSetAttribute(hmma_gemm<STAGES, RELU, OMODE>,
                         cudaFuncAttributeMaxDynamicSharedMemorySize, SMEMB);
    dim3 g(N / 128, M / 128);
    hmma_gemm<STAGES, RELU, OMODE><<<g, 256, SMEMB>>>(
        a0, a1, b0, b1, bias, cf, c0, c1, M, N, K);
}

extern "C" void kernel_launch(void* const* d_in, const int* in_sizes, int n_in,
                              void* d_out, int out_size)
{
    const float* x      = (const float*)d_in[0];
    const int*   labels = (const int*)  d_in[1];
    const float* ew[4]  = {(const float*)d_in[2], (const float*)d_in[4],
                           (const float*)d_in[6], (const float*)d_in[8]};
    const float* eb[4]  = {(const float*)d_in[3], (const float*)d_in[5],
                           (const float*)d_in[7], (const float*)d_in[9]};
    const float* dw[4]  = {(const float*)d_in[10], (const float*)d_in[12],
                           (const float*)d_in[14], (const float*)d_in[16]};
    const float* db[4]  = {(const float*)d_in[11], (const float*)d_in[13],
                           (const float*)d_in[15], (const float*)d_in[17]};
    const float* cb     = (const float*)d_in[18];
    float* out = (float*)d_out;

    float *res, *xq;
    __nv_bfloat16 *dA0, *dA1, *dB0, *dB1, *dw0, *dw1, *ew0, *ew1;
    cudaGetSymbolAddress((void**)&res,  g_res);
    cudaGetSymbolAddress((void**)&xq,   g_xq);
    cudaGetSymbolAddress((void**)&dA0,  g_dA0);
    cudaGetSymbolAddress((void**)&dA1,  g_dA1);
    cudaGetSymbolAddress((void**)&dB0,  g_dB0);
    cudaGetSymbolAddress((void**)&dB1,  g_dB1);
    cudaGetSymbolAddress((void**)&dw0,  g_dw0);
    cudaGetSymbolAddress((void**)&dw1,  g_dw1);
    cudaGetSymbolAddress((void**)&ew0,  g_ew0);
    cudaGetSymbolAddress((void**)&ew1,  g_ew1);

    static const int RQ_SMEM = CBK * 129 * sizeof(float);
    cudaFuncSetAttribute(rq_level, cudaFuncAttributeMaxDynamicSharedMemorySize, RQ_SMEM);

    // weight tables ([N,K] after transpose)
    const int eLN[4] = {2048, 1024, 512, 128};
    const int eLK[4] = {768, 2048, 1024, 512};
    const int dLN[4] = {512, 1024, 2048, 768};
    const int dLK[4] = {128, 512, 1024, 2048};
    size_t eoff[4], doff[4];
    {
        size_t o = 0;
        for (int i = 0; i < 4; i++) { eoff[i] = o; o += (size_t)eLN[i] * eLK[i]; }
        o = 0;
        for (int i = 0; i < 4; i++) { doff[i] = o; o += (size_t)dLN[i] * dLK[i]; }
    }

    // ---- preprocess weights (transpose + bf16 hi/lo split) ----
    for (int i = 0; i < 4; i++) {
        dim3 b(32, 32);
        dim3 ge(eLN[i] / 32, eLK[i] / 32);
        k_wprep2<<<ge, b>>>(ew[i], ew0 + eoff[i], ew1 + eoff[i], eLK[i], eLN[i]);
        dim3 gd(dLN[i] / 32, dLK[i] / 32);
        k_wprep2<<<gd, b>>>(dw[i], dw0 + doff[i], dw1 + doff[i], dLK[i], dLN[i]);
    }

    // ---- expert grouping ----
    k_zero_counts<<<1, 32>>>();
    k_hist   <<<BROWS / 256, 256>>>(labels);
    k_scan   <<<1, 1>>>();
    k_scatter<<<BROWS / 256, 256>>>(labels);

    // ---- encoder (bf16x3 tensor cores; flips handled by margin+repair) ----
    k_split<<<(BROWS * 768 + 255) / 256, 256>>>(x, dA0, dA1, BROWS * 768);
    launch_hmma<2, true, 1>(dA0, dA1, ew0 + eoff[0], ew1 + eoff[0], eb[0],
                            nullptr, dB0, dB1, BROWS, 2048, 768);
    launch_hmma<2, true, 1>(dB0, dB1, ew0 + eoff[1], ew1 + eoff[1], eb[1],
                            nullptr, dA0, dA1, BROWS, 1024, 2048);
    launch_hmma<2, true, 1>(dA0, dA1, ew0 + eoff[2], ew1 + eoff[2], eb[2],
                            nullptr, dB0, dB1, BROWS, 512, 1024);
    launch_hmma<2, false, 0>(dB0, dB1, ew0 + eoff[3], ew1 + eoff[3], eb[3],
                             res, nullptr, nullptr, BROWS, 128, 512);

    // ---- residual quantization (approx with margin flags) ----
    k_rq_init<<<(BROWS * ZD + 255) / 256, 256>>>();
    dim3 rqg((BROWS + RQ_ROWS - 1) / RQ_ROWS, NUM_EXPERTS);
    for (int l = 0; l < NUM_LEVELS; l++)
        rq_level<<<rqg, 256, RQ_SMEM>>>(cb, out + IDX_OFF, l);

    // ---- exact repair of flagged rows ----
    k_compact<<<BROWS / 256, 256>>>();
    k_repair<<<256, 256>>>(x, labels, ew[0], eb[0], ew[1], eb[1],
                           ew[2], eb[2], ew[3], eb[3], cb, out + IDX_OFF);

    k_loss_finish<<<1, 1024>>>(out + LOSS_OFF);

    // ---- x_q output + decoder input split (fused) ----
    k_xq_out<<<(BROWS * ZD + 255) / 256, 256>>>(xq, out + XQ_OFF, dA0, dA1);

    // ---- decoder (bf16x3 HMMA, STAGES=2 -> 2 CTAs/SM) ----
    launch_hmma<2, true, 1>(dA0, dA1, dw0 + doff[0], dw1 + doff[0], db[0],
                            nullptr, dB0, dB1, BROWS, 512, 128);
    launch_hmma<2, true, 1>(dB0, dB1, dw0 + doff[1], dw1 + doff[1], db[1],
                            nullptr, dA0, dA1, BROWS, 1024, 512);
    launch_hmma<2, true, 1>(dA0, dA1, dw0 + doff[2], dw1 + doff[2], db[2],
                            nullptr, dB0, dB1, BROWS, 2048, 1024);
    launch_hmma<2, false, 0>(dB0, dB1, dw0 + doff[3], dw1 + doff[3], db[3],
                             out + OUT_OFF, nullptr, nullptr, BROWS, 768, 2048);
}

// round 16
// speedup vs baseline: 4.4609x; 4.4609x over previous
#include <cuda_runtime.h>
#include <cuda_bf16.h>
#include <cstdint>

#define BROWS 32768
#define NUM_EXPERTS 10
#define NUM_LEVELS 4
#define CBK 256
#define ZD 128
#define BETA 0.001f
#define RQ_ROWS 32
#define TAU 1e-5f

#define OUT_OFF  0
#define LOSS_OFF (32768 * 768)
#define IDX_OFF  (LOSS_OFF + 1)
#define XQ_OFF   (IDX_OFF + 32768 * 4)

// ---------------------------------------------------------------------------
// Device scratch
// ---------------------------------------------------------------------------
__device__ float g_res [32768 * ZD];
__device__ float g_xq  [32768 * ZD];
__device__ float g_lossbuf[32768];
__device__ int   g_counts[NUM_EXPERTS];
__device__ int   g_cursor[NUM_EXPERTS];
__device__ int   g_offsets[NUM_EXPERTS + 1];
__device__ int   g_perm[32768];
__device__ int   g_rowflag[32768];
__device__ int   g_replist[32768];
__device__ int   g_nrep;
__device__ int   g_npad;

// repair batch buffers (exact fp32 path over compacted flagged rows)
__device__ float g_gx  [32768u * 768u];
__device__ float g_rb0 [32768u * 2048u];
__device__ float g_rb1 [32768u * 1024u];
__device__ float g_rz  [32768u * ZD];

// bf16 hi/lo activation ping-pong (encoder + decoder) + split weights
__device__ __nv_bfloat16 g_dA0[32768u * 1024u];
__device__ __nv_bfloat16 g_dA1[32768u * 1024u];
__device__ __nv_bfloat16 g_dB0[32768u * 2048u];
__device__ __nv_bfloat16 g_dB1[32768u * 2048u];
#define W_TOTAL 4259840
__device__ __nv_bfloat16 g_dw0[W_TOTAL];
__device__ __nv_bfloat16 g_dw1[W_TOTAL];
__device__ __nv_bfloat16 g_ew0[W_TOTAL];
__device__ __nv_bfloat16 g_ew1[W_TOTAL];

// ---------------------------------------------------------------------------
// PTX helpers
// ---------------------------------------------------------------------------
__device__ __forceinline__ uint32_t smem_u32(const void* p) {
    uint32_t a;
    asm("{ .reg .u64 t; cvta.to.shared.u64 t, %1; cvt.u32.u64 %0, t; }"
        : "=r"(a) : "l"(p));
    return a;
}
__device__ __forceinline__ void cpa16(uint32_t dst, const void* src) {
    asm volatile("cp.async.cg.shared.global [%0], [%1], 16;" :: "r"(dst), "l"(src) : "memory");
}
#define CP_COMMIT() asm volatile("cp.async.commit_group;" ::: "memory")
#define CP_WAIT(n)  asm volatile("cp.async.wait_group %0;" :: "n"(n) : "memory")

#define LDSM4(r0, r1, r2, r3, addr) \
    asm volatile("ldmatrix.sync.aligned.m8n8.x4.shared.b16 {%0,%1,%2,%3}, [%4];" \
        : "=r"(r0), "=r"(r1), "=r"(r2), "=r"(r3) : "r"(addr))

#define MMA16816(acc, a, b0, b1) \
    asm volatile("mma.sync.aligned.m16n8k16.row.col.f32.bf16.bf16.f32 " \
        "{%0,%1,%2,%3}, {%4,%5,%6,%7}, {%8,%9}, {%0,%1,%2,%3};" \
        : "+f"((acc)[0]), "+f"((acc)[1]), "+f"((acc)[2]), "+f"((acc)[3]) \
        : "r"((a)[0]), "r"((a)[1]), "r"((a)[2]), "r"((a)[3]), "r"(b0), "r"(b1))

#define FMA2(d, a, b) \
    asm("fma.rn.f32x2 %0, %1, %2, %0;" : "+l"(d) : "l"(a), "l"(b))
#define PACK2(out, x) \
    asm("mov.b64 %0, {%1, %1};" : "=l"(out) : "f"(x))
#define UNPACK2(lo, hi, in) \
    asm("mov.b64 {%0, %1}, %2;" : "=f"(lo), "=f"(hi) : "l"(in))

// ---------------------------------------------------------------------------
// HMMA bf16x3 GEMM (validated; STAGES=2 -> 2 CTAs/SM).
// ---------------------------------------------------------------------------
#define TSTRIDE 40
#define SUBTILE (128 * TSTRIDE * 2)

template <int STAGES, bool RELU, int OMODE>
__global__ __launch_bounds__(256)
void hmma_gemm(const __nv_bfloat16* __restrict__ A0, const __nv_bfloat16* __restrict__ A1,
               const __nv_bfloat16* __restrict__ B0, const __nv_bfloat16* __restrict__ B1,
               const float* __restrict__ bias, float* __restrict__ Cf,
               __nv_bfloat16* __restrict__ C0, __nv_bfloat16* __restrict__ C1,
               int M, int N, int K)
{
    constexpr int STAGE = 4 * SUBTILE;
    extern __shared__ char smem[];
    const uint32_t sbase = smem_u32(smem);

    const int tid  = threadIdx.x;
    const int lane = tid & 31;
    const int wid  = tid >> 5;
    const int wm   = wid & 3;
    const int wn   = wid >> 2;
    const int m0   = blockIdx.y * 128;
    const int n0   = blockIdx.x * 128;
    const int nch  = K >> 5;

    float acc[2][8][4];
#pragma unroll
    for (int a = 0; a < 2; a++)
#pragma unroll
        for (int b = 0; b < 8; b++)
#pragma unroll
            for (int c = 0; c < 4; c++) acc[a][b][c] = 0.f;

    auto load_stage = [&](int stg, int k0) {
        const uint32_t sb_ = sbase + stg * STAGE;
#pragma unroll
        for (int ii = 0; ii < 2; ii++) {
            const int i = tid + ii * 256;
            const int r = i >> 2, c = i & 3;
            const uint32_t so = r * 80 + c * 16;
            const size_t ga = (size_t)(m0 + r) * K + k0 + c * 8;
            const size_t gb = (size_t)(n0 + r) * K + k0 + c * 8;
            cpa16(sb_ + so,               A0 + ga);
            cpa16(sb_ + SUBTILE + so,     A1 + ga);
            cpa16(sb_ + 2 * SUBTILE + so, B0 + gb);
            cpa16(sb_ + 3 * SUBTILE + so, B1 + gb);
        }
    };

#pragma unroll
    for (int s = 0; s < STAGES; s++) {
        if (s < nch) load_stage(s, s * 32);
        CP_COMMIT();
    }

    const int lrow = lane & 15;
    const int lsel = (lane >> 4) << 3;

    for (int ch = 0; ch < nch; ch++) {
        CP_WAIT(STAGES - 1);
        __syncthreads();
        const uint32_t sb = sbase + (ch % STAGES) * STAGE;
        const uint32_t Ahb = sb, Alb = sb + SUBTILE;
        const uint32_t Bhb = sb + 2 * SUBTILE, Blb = sb + 3 * SUBTILE;

#pragma unroll
        for (int kk = 0; kk < 32; kk += 16) {
            uint32_t ah[2][4], al[2][4];
#pragma unroll
            for (int mt = 0; mt < 2; mt++) {
                uint32_t off = ((wm * 32 + mt * 16 + lrow) * TSTRIDE + kk + lsel) * 2;
                LDSM4(ah[mt][0], ah[mt][1], ah[mt][2], ah[mt][3], Ahb + off);
                LDSM4(al[mt][0], al[mt][1], al[mt][2], al[mt][3], Alb + off);
            }
            uint32_t bh[8][2], bl[8][2];
#pragma unroll
            for (int g = 0; g < 4; g++) {
                uint32_t off = ((wn * 64 + g * 16 + lrow) * TSTRIDE + kk + lsel) * 2;
                uint32_t t0, t1, t2, t3;
                LDSM4(t0, t1, t2, t3, Bhb + off);
                bh[2*g][0] = t0;   bh[2*g][1] = t2;
                bh[2*g+1][0] = t1; bh[2*g+1][1] = t3;
                LDSM4(t0, t1, t2, t3, Blb + off);
                bl[2*g][0] = t0;   bl[2*g][1] = t2;
                bl[2*g+1][0] = t1; bl[2*g+1][1] = t3;
            }
#pragma unroll
            for (int mt = 0; mt < 2; mt++)
#pragma unroll
                for (int nt = 0; nt < 8; nt++) {
                    MMA16816(acc[mt][nt], ah[mt], bh[nt][0], bh[nt][1]);
                    MMA16816(acc[mt][nt], ah[mt], bl[nt][0], bl[nt][1]);
                    MMA16816(acc[mt][nt], al[mt], bh[nt][0], bh[nt][1]);
                }
        }
        __syncthreads();
        if (ch + STAGES < nch) load_stage(ch % STAGES, (ch + STAGES) * 32);
        CP_COMMIT();
    }

    const int gid = lane >> 2;
    const int tg  = lane & 3;
#pragma unroll
    for (int mt = 0; mt < 2; mt++) {
#pragma unroll
        for (int nt = 0; nt < 8; nt++) {
            const int col = n0 + wn * 64 + nt * 8 + tg * 2;
            const float2 bb = __ldg((const float2*)(bias + col));
#pragma unroll
            for (int h = 0; h < 2; h++) {
                const int row = m0 + wm * 32 + mt * 16 + gid + h * 8;
                float v0 = acc[mt][nt][2*h]   + bb.x;
                float v1 = acc[mt][nt][2*h+1] + bb.y;
                if (RELU) { v0 = fmaxf(v0, 0.f); v1 = fmaxf(v1, 0.f); }
                if (OMODE == 0) {
                    *(float2*)(Cf + (size_t)row * N + col) = make_float2(v0, v1);
                } else {
                    __nv_bfloat16 h0 = __float2bfloat16(v0);
                    __nv_bfloat16 h1 = __float2bfloat16(v1);
                    __nv_bfloat162 p0; p0.x = h0; p0.y = h1;
                    __nv_bfloat162 p1;
                    p1.x = __float2bfloat16(v0 - __bfloat162float(h0));
                    p1.y = __float2bfloat16(v1 - __bfloat162float(h1));
                    *(__nv_bfloat162*)(C0 + (size_t)row * N + col) = p0;
                    *(__nv_bfloat162*)(C1 + (size_t)row * N + col) = p1;
                }
            }
        }
    }
}

// ---------------------------------------------------------------------------
// Exact fp32 FFMA2 SGEMM (R12/R14 validated, bitwise = reference chain).
// Dynamic row-limit via device counter (graph-safe): blocks beyond the
// compacted batch exit immediately.
// ---------------------------------------------------------------------------
template <bool RELU>
__global__ __launch_bounds__(256, 2)
void sgemm_dyn(const float* __restrict__ A, const float* __restrict__ W,
               const float* __restrict__ bias, float* __restrict__ C,
               int M, int N, int K)
{
    if (blockIdx.y * 128 >= g_npad) return;

    __shared__ float As[2][16][128];
    __shared__ float Bs[3][16][128];

    const int t  = threadIdx.x;
    const int bm = blockIdx.y;
    const int bn = blockIdx.x;
    const int tx = t & 15;
    const int ty = t >> 4;

    const int ar0 = t >> 2;
    const int akq = (t & 3) * 4;
    const int bk0 = t >> 5;
    const int bcq = (t & 31) * 4;

    const float* Ag = A + (size_t)(bm * 128) * K;
    const float* Wg = W + bn * 128;

    const uint32_t bs_base0 = smem_u32(&Bs[0][bk0][bcq]);
    const uint32_t bs_base1 = smem_u32(&Bs[0][8 + bk0][bcq]);
    const uint32_t BS_STAGE = 16 * 128 * 4;

    unsigned long long acc2[8][4];
#pragma unroll
    for (int i = 0; i < 8; i++)
#pragma unroll
        for (int j = 0; j < 4; j++) acc2[i][j] = 0ull;

    const int nch = K >> 4;

    float4 pa0 = *(const float4*)(Ag + (size_t)ar0 * K + akq);
    float4 pa1 = *(const float4*)(Ag + (size_t)(64 + ar0) * K + akq);
    cpa16(bs_base0, Wg + (size_t)bk0 * N + bcq);
    cpa16(bs_base1, Wg + (size_t)(8 + bk0) * N + bcq);
    CP_COMMIT();
    if (nch > 1) {
        cpa16(bs_base0 + BS_STAGE, Wg + (size_t)(16 + bk0) * N + bcq);
        cpa16(bs_base1 + BS_STAGE, Wg + (size_t)(16 + 8 + bk0) * N + bcq);
    }
    CP_COMMIT();

    for (int ch = 0; ch < nch; ch++) {
        const int s  = ch & 1;
        const int bs = ch % 3;
        As[s][akq + 0][ar0] = pa0.x;
        As[s][akq + 1][ar0] = pa0.y;
        As[s][akq + 2][ar0] = pa0.z;
        As[s][akq + 3][ar0] = pa0.w;
        As[s][akq + 0][64 + ar0] = pa1.x;
        As[s][akq + 1][64 + ar0] = pa1.y;
        As[s][akq + 2][64 + ar0] = pa1.z;
        As[s][akq + 3][64 + ar0] = pa1.w;
        CP_WAIT(1);
        __syncthreads();

        if (ch + 2 < nch) {
            const int k0 = (ch + 2) << 4;
            const uint32_t dst = (uint32_t)(((ch + 2) % 3) * BS_STAGE);
            cpa16(bs_base0 + dst, Wg + (size_t)(k0 + bk0) * N + bcq);
            cpa16(bs_base1 + dst, Wg + (size_t)(k0 + 8 + bk0) * N + bcq);
        }
        CP_COMMIT();
        if (ch + 1 < nch) {
            const int k0 = (ch + 1) << 4;
            pa0 = *(const float4*)(Ag + (size_t)ar0 * K + k0 + akq);
            pa1 = *(const float4*)(Ag + (size_t)(64 + ar0) * K + k0 + akq);
        }

#pragma unroll
        for (int k = 0; k < 16; k++) {
            float a[8];
            *(float4*)&a[0] = *(const float4*)&As[s][k][ty * 8];
            *(float4*)&a[4] = *(const float4*)&As[s][k][ty * 8 + 4];
            const ulonglong2 b01 = *(const ulonglong2*)&Bs[bs][k][tx * 8];
            const ulonglong2 b23 = *(const ulonglong2*)&Bs[bs][k][tx * 8 + 4];
            unsigned long long bp[4] = {b01.x, b01.y, b23.x, b23.y};
            unsigned long long ap[8];
#pragma unroll
            for (int i = 0; i < 8; i++) PACK2(ap[i], a[i]);
#pragma unroll
            for (int i = 0; i < 8; i++)
#pragma unroll
                for (int j = 0; j < 4; j++)
                    FMA2(acc2[i][j], ap[i], bp[j]);
        }
    }

    const int crow0 = bm * 128 + ty * 8;
    const int ccol0 = bn * 128 + tx * 8;
    float bb[8];
#pragma unroll
    for (int j = 0; j < 8; j++) bb[j] = bias[ccol0 + j];

#pragma unroll
    for (int i = 0; i < 8; i++) {
        float v[8];
#pragma unroll
        for (int j = 0; j < 4; j++) {
            float lo, hi;
            UNPACK2(lo, hi, acc2[i][j]);
            float x0 = lo + bb[2 * j];
            float x1 = hi + bb[2 * j + 1];
            if (RELU) { x0 = fmaxf(x0, 0.f); x1 = fmaxf(x1, 0.f); }
            v[2 * j] = x0;
            v[2 * j + 1] = x1;
        }
        float* cp = C + (size_t)(crow0 + i) * N + ccol0;
        *(float4*)(cp)     = *(float4*)&v[0];
        *(float4*)(cp + 4) = *(float4*)&v[4];
    }
}

// ---------------------------------------------------------------------------
// Preprocessing
// ---------------------------------------------------------------------------
__global__ void k_wprep2(const float* __restrict__ W, __nv_bfloat16* __restrict__ T0,
                         __nv_bfloat16* __restrict__ T1, int K, int N)
{
    __shared__ float t[32][33];
    int n = blockIdx.x * 32 + threadIdx.x;
    int k = blockIdx.y * 32 + threadIdx.y;
    t[threadIdx.y][threadIdx.x] = W[(size_t)k * N + n];
    __syncthreads();
    int nn = blockIdx.x * 32 + threadIdx.y;
    int kk = blockIdx.y * 32 + threadIdx.x;
    float v = t[threadIdx.x][threadIdx.y];
    __nv_bfloat16 h = __float2bfloat16(v);
    T0[(size_t)nn * K + kk] = h;
    T1[(size_t)nn * K + kk] = __float2bfloat16(v - __bfloat162float(h));
}

__global__ void k_split(const float* __restrict__ src, __nv_bfloat16* __restrict__ o0,
                        __nv_bfloat16* __restrict__ o1, int n)
{
    int i = blockIdx.x * 256 + threadIdx.x;
    if (i < n) {
        float v = src[i];
        __nv_bfloat16 h = __float2bfloat16(v);
        o0[i] = h;
        o1[i] = __float2bfloat16(v - __bfloat162float(h));
    }
}

__global__ void k_xq_out(const float* __restrict__ xq, float* __restrict__ dst,
                         __nv_bfloat16* __restrict__ o0, __nv_bfloat16* __restrict__ o1)
{
    int i = blockIdx.x * 256 + threadIdx.x;
    if (i < BROWS * ZD) {
        float v = xq[i];
        dst[i] = v;
        __nv_bfloat16 h = __float2bfloat16(v);
        o0[i] = h;
        o1[i] = __float2bfloat16(v - __bfloat162float(h));
    }
}

// ---------------------------------------------------------------------------
// Expert counting-sort + init
// ---------------------------------------------------------------------------
__global__ void k_zero_counts() {
    int t = threadIdx.x;
    if (t < NUM_EXPERTS) { g_counts[t] = 0; g_cursor[t] = 0; }
    if (t == 0) { g_nrep = 0; g_npad = 0; }
}
__global__ void k_hist(const int* __restrict__ labels) {
    int i = blockIdx.x * blockDim.x + threadIdx.x;
    if (i < BROWS) atomicAdd(&g_counts[labels[i]], 1);
}
__global__ void k_scan() {
    if (threadIdx.x == 0) {
        int s = 0;
        for (int e = 0; e < NUM_EXPERTS; e++) { g_offsets[e] = s; s += g_counts[e]; }
        g_offsets[NUM_EXPERTS] = s;
    }
}
__global__ void k_scatter(const int* __restrict__ labels) {
    int i = blockIdx.x * blockDim.x + threadIdx.x;
    if (i < BROWS) {
        int e = labels[i];
        int p = atomicAdd(&g_cursor[e], 1);
        g_perm[g_offsets[e] + p] = i;
    }
}
__global__ void k_rq_init() {
    int i = blockIdx.x * blockDim.x + threadIdx.x;
    if (i < BROWS * ZD) g_xq[i] = 0.f;
    if (i < BROWS) { g_lossbuf[i] = 0.f; g_rowflag[i] = 0; }
}

// ---------------------------------------------------------------------------
// Residual quantization with top-2 margin flagging (TAU relative).
// ---------------------------------------------------------------------------
__global__ void rq_level(const float* __restrict__ cb,
                         float* __restrict__ idx_out, int level)
{
    extern __shared__ float c_sh[];
    __shared__ float res_sh[ZD];
    __shared__ float cn_sh[CBK];
    __shared__ float s_ws[8];
    __shared__ int   s_wi[8];
    __shared__ float s_w2[8];
    __shared__ float s_red[4];
    __shared__ int   s_kmin;

    const int e     = blockIdx.y;
    const int start = g_offsets[e];
    const int end   = g_offsets[e + 1];
    const int rbase = start + blockIdx.x * RQ_ROWS;
    if (rbase >= end) return;

    const int t = threadIdx.x;
    const int lane = t & 31;
    const int warp = t >> 5;
    const float INF = __int_as_float(0x7f800000);

    const float* cbl = cb + ((size_t)level * NUM_EXPERTS + e) * CBK * ZD;
    for (int i = t; i < (CBK * ZD) / 4; i += 256) {
        float4 v = ((const float4*)cbl)[i];
        int k = i >> 5;
        int j = (i & 31) << 2;
        float* d = &c_sh[k * 129 + j];
        d[0] = v.x; d[1] = v.y; d[2] = v.z; d[3] = v.w;
    }
    __syncthreads();

    {
        const float* cr = &c_sh[t * 129];
        float s = 0.f;
#pragma unroll 8
        for (int j = 0; j < ZD; j++) s += cr[j] * cr[j];
        cn_sh[t] = s;
    }
    __syncthreads();

    const int nrows = min(RQ_ROWS, end - rbase);
    for (int i = 0; i < nrows; i++) {
        const int row = g_perm[rbase + i];
        if (t < ZD) res_sh[t] = g_res[row * ZD + t];
        __syncthreads();

        float dot = 0.f;
        const float* cr = &c_sh[t * 129];
#pragma unroll 8
        for (int j = 0; j < ZD; j++) dot += cr[j] * res_sh[j];
        float s1 = cn_sh[t] - 2.f * dot;
        int   i1 = t;
        float s2 = INF;

#pragma unroll
        for (int o = 16; o > 0; o >>= 1) {
            float t1 = __shfl_down_sync(0xffffffffu, s1, o);
            int   j1 = __shfl_down_sync(0xffffffffu, i1, o);
            float t2 = __shfl_down_sync(0xffffffffu, s2, o);
            if (t1 < s1 || (t1 == s1 && j1 < i1)) {
                s2 = fminf(s1, t2);
                s1 = t1; i1 = j1;
            } else {
                s2 = fminf(s2, t1);
            }
        }
        if (lane == 0) { s_ws[warp] = s1; s_wi[warp] = i1; s_w2[warp] = s2; }
        __syncthreads();
        if (t == 0) {
            float bs = s_ws[0]; int bi = s_wi[0]; float b2 = s_w2[0];
#pragma unroll
            for (int w = 1; w < 8; w++) {
                float u1 = s_ws[w]; int u = s_wi[w]; float u2 = s_w2[w];
                if (u1 < bs || (u1 == bs && u < bi)) {
                    b2 = fminf(bs, u2);
                    bs = u1; bi = u;
                } else {
                    b2 = fminf(b2, u1);
                }
            }
            s_kmin = bi;
            if (b2 - bs < TAU * (1.0f + fabsf(bs))) g_rowflag[row] = 1;
        }
        __syncthreads();
        const int kmin = s_kmin;

        float sq = 0.f;
        if (t < ZD) {
            float q  = c_sh[kmin * 129 + t];
            float nr = res_sh[t] - q;
            g_res[row * ZD + t] = nr;
            g_xq [row * ZD + t] += q;
            sq = nr * nr;
        }
#pragma unroll
        for (int o = 16; o > 0; o >>= 1) sq += __shfl_down_sync(0xffffffffu, sq, o);
        if (t < ZD && lane == 0) s_red[warp] = sq;
        __syncthreads();
        if (t == 0) {
            g_lossbuf[row] += s_red[0] + s_red[1] + s_red[2] + s_red[3];
            idx_out[row * 4 + level] = (float)kmin;
        }
        __syncthreads();
    }
}

__global__ void k_compact() {
    int i = blockIdx.x * blockDim.x + threadIdx.x;
    if (i < BROWS && g_rowflag[i]) {
        int p = atomicAdd(&g_nrep, 1);
        g_replist[p] = i;
    }
}
__global__ void k_padcount() {
    if (threadIdx.x == 0) g_npad = ((g_nrep + 127) / 128) * 128;
}

// gather flagged x rows into dense buffer; zero the pad rows
__global__ void k_gather(const float* __restrict__ x)
{
    const int fi = blockIdx.x;
    if (fi >= g_npad) return;
    const int t = threadIdx.x;
    float* dst = g_gx + (size_t)fi * 768;
    if (fi < g_nrep) {
        const float* src = x + (size_t)g_replist[fi] * 768;
        for (int j = t; j < 768; j += 256) dst[j] = src[j];
    } else {
        for (int j = t; j < 768; j += 256) dst[j] = 0.f;
    }
}

// ---------------------------------------------------------------------------
// Exact RQ redo for flagged rows (z from the exact repair pipeline).
// Identical score/argmin/update/loss expressions to rq_level.
// ---------------------------------------------------------------------------
__global__ __launch_bounds__(256)
void rq_redo(const int* __restrict__ labels, const float* __restrict__ cb,
             float* __restrict__ idx_out)
{
    const int fi = blockIdx.x;
    if (fi >= g_nrep) return;

    __shared__ float res_s[ZD];
    __shared__ float xq_s[ZD];
    __shared__ float s_ws[8];
    __shared__ int   s_wi[8];
    __shared__ float s_red[4];
    __shared__ int   s_kmin;
    __shared__ float s_loss;

    const int t = threadIdx.x;
    const int lane = t & 31;
    const int warp = t >> 5;
    const int row = g_replist[fi];

    if (t < ZD) { res_s[t] = g_rz[(size_t)fi * ZD + t]; xq_s[t] = 0.f; }
    if (t == 0) s_loss = 0.f;
    __syncthreads();

    const int e = labels[row];
    for (int l = 0; l < NUM_LEVELS; l++) {
        const float* cbl = cb + ((size_t)l * NUM_EXPERTS + e) * CBK * ZD;
        const float* cr = cbl + (size_t)t * ZD;
        float cn = 0.f, dot = 0.f;
#pragma unroll 8
        for (int j = 0; j < ZD; j++) cn  += cr[j] * cr[j];
#pragma unroll 8
        for (int j = 0; j < ZD; j++) dot += cr[j] * res_s[j];
        float sc = cn - 2.f * dot;
        int   ix = t;
#pragma unroll
        for (int o = 16; o > 0; o >>= 1) {
            float sc2 = __shfl_down_sync(0xffffffffu, sc, o);
            int   ix2 = __shfl_down_sync(0xffffffffu, ix, o);
            if (sc2 < sc || (sc2 == sc && ix2 < ix)) { sc = sc2; ix = ix2; }
        }
        if (lane == 0) { s_ws[warp] = sc; s_wi[warp] = ix; }
        __syncthreads();
        if (t == 0) {
            float bs = s_ws[0]; int bi = s_wi[0];
#pragma unroll
            for (int w = 1; w < 8; w++) {
                float u = s_ws[w]; int ui = s_wi[w];
                if (u < bs || (u == bs && ui < bi)) { bs = u; bi = ui; }
            }
            s_kmin = bi;
        }
        __syncthreads();
        const int kmin = s_kmin;

        float sq = 0.f;
        if (t < ZD) {
            float q  = cbl[(size_t)kmin * ZD + t];
            float nr = res_s[t] - q;
            res_s[t] = nr;
            xq_s[t] += q;
            sq = nr * nr;
        }
        __syncthreads();
#pragma unroll
        for (int o = 16; o > 0; o >>= 1) sq += __shfl_down_sync(0xffffffffu, sq, o);
        if (t < ZD && lane == 0) s_red[warp] = sq;
        __syncthreads();
        if (t == 0) {
            s_loss += s_red[0] + s_red[1] + s_red[2] + s_red[3];
            idx_out[row * 4 + l] = (float)kmin;
        }
        __syncthreads();
    }
    if (t < ZD) g_xq[(size_t)row * ZD + t] = xq_s[t];
    if (t == 0) g_lossbuf[row] = s_loss;
}

__global__ void k_loss_finish(float* __restrict__ loss_out) {
    __shared__ float sm[1024];
    float s = 0.f;
    for (int i = threadIdx.x; i < BROWS; i += 1024) s += g_lossbuf[i];
    sm[threadIdx.x] = s;
    __syncthreads();
    for (int k = 512; k > 0; k >>= 1) {
        if (threadIdx.x < k) sm[threadIdx.x] += sm[threadIdx.x + k];
        __syncthreads();
    }
    if (threadIdx.x == 0)
        loss_out[0] = sm[0] * (1.f + BETA) / ((float)BROWS * (float)ZD);
}

// ---------------------------------------------------------------------------
// Host launch
// ---------------------------------------------------------------------------
template <int STAGES, bool RELU, int OMODE>
static void launch_hmma(const __nv_bfloat16* a0, const __nv_bfloat16* a1,
                        const __nv_bfloat16* b0, const __nv_bfloat16* b1,
                        const float* bias, float* cf,
                        __nv_bfloat16* c0, __nv_bfloat16* c1,
                        int M, int N, int K)
{
    constexpr int SMEMB = STAGES * 4 * SUBTILE;
    cudaFuncSetAttribute(hmma_gemm<STAGES, RELU, OMODE>,
                         cudaFuncAttributeMaxDynamicSharedMemorySize, SMEMB);
    dim3 g(N / 128, M / 128);
    hmma_gemm<STAGES, RELU, OMODE><<<g, 256, SMEMB>>>(
        a0, a1, b0, b1, bias, cf, c0, c1, M, N, K);
}

template <bool RELU>
static void launch_repair_sgemm(const float* A, const float* W, const float* b,
                                float* C, int N, int K)
{
    dim3 grid(N / 128, BROWS / 128);   // worst-case; blocks early-exit on g_npad
    sgemm_dyn<RELU><<<grid, 256>>>(A, W, b, C, BROWS, N, K);
}

extern "C" void kernel_launch(void* const* d_in, const int* in_sizes, int n_in,
                              void* d_out, int out_size)
{
    const float* x      = (const float*)d_in[0];
    const int*   labels = (const int*)  d_in[1];
    const float* ew[4]  = {(const float*)d_in[2], (const float*)d_in[4],
                           (const float*)d_in[6], (const float*)d_in[8]};
    const float* eb[4]  = {(const float*)d_in[3], (const float*)d_in[5],
                           (const float*)d_in[7], (const float*)d_in[9]};
    const float* dw[4]  = {(const float*)d_in[10], (const float*)d_in[12],
                           (const float*)d_in[14], (const float*)d_in[16]};
    const float* db[4]  = {(const float*)d_in[11], (const float*)d_in[13],
                           (const float*)d_in[15], (const float*)d_in[17]};
    const float* cb     = (const float*)d_in[18];
    float* out = (float*)d_out;

    float *res, *xq, *gx, *rb0, *rb1, *rz;
    __nv_bfloat16 *dA0, *dA1, *dB0, *dB1, *dw0, *dw1, *ew0, *ew1;
    cudaGetSymbolAddress((void**)&res,  g_res);
    cudaGetSymbolAddress((void**)&xq,   g_xq);
    cudaGetSymbolAddress((void**)&gx,   g_gx);
    cudaGetSymbolAddress((void**)&rb0,  g_rb0);
    cudaGetSymbolAddress((void**)&rb1,  g_rb1);
    cudaGetSymbolAddress((void**)&rz,   g_rz);
    cudaGetSymbolAddress((void**)&dA0,  g_dA0);
    cudaGetSymbolAddress((void**)&dA1,  g_dA1);
    cudaGetSymbolAddress((void**)&dB0,  g_dB0);
    cudaGetSymbolAddress((void**)&dB1,  g_dB1);
    cudaGetSymbolAddress((void**)&dw0,  g_dw0);
    cudaGetSymbolAddress((void**)&dw1,  g_dw1);
    cudaGetSymbolAddress((void**)&ew0,  g_ew0);
    cudaGetSymbolAddress((void**)&ew1,  g_ew1);

    static const int RQ_SMEM = CBK * 129 * sizeof(float);
    cudaFuncSetAttribute(rq_level, cudaFuncAttributeMaxDynamicSharedMemorySize, RQ_SMEM);

    const int eLN[4] = {2048, 1024, 512, 128};
    const int eLK[4] = {768, 2048, 1024, 512};
    const int dLN[4] = {512, 1024, 2048, 768};
    const int dLK[4] = {128, 512, 1024, 2048};
    size_t eoff[4], doff[4];
    {
        size_t o = 0;
        for (int i = 0; i < 4; i++) { eoff[i] = o; o += (size_t)eLN[i] * eLK[i]; }
        o = 0;
        for (int i = 0; i < 4; i++) { doff[i] = o; o += (size_t)dLN[i] * dLK[i]; }
    }

    // ---- preprocess weights ----
    for (int i = 0; i < 4; i++) {
        dim3 b(32, 32);
        dim3 ge(eLN[i] / 32, eLK[i] / 32);
        k_wprep2<<<ge, b>>>(ew[i], ew0 + eoff[i], ew1 + eoff[i], eLK[i], eLN[i]);
        dim3 gd(dLN[i] / 32, dLK[i] / 32);
        k_wprep2<<<gd, b>>>(dw[i], dw0 + doff[i], dw1 + doff[i], dLK[i], dLN[i]);
    }

    // ---- expert grouping ----
    k_zero_counts<<<1, 32>>>();
    k_hist   <<<BROWS / 256, 256>>>(labels);
    k_scan   <<<1, 1>>>();
    k_scatter<<<BROWS / 256, 256>>>(labels);

    // ---- encoder (bf16x3 tensor cores; flips caught by margin+repair) ----
    k_split<<<(BROWS * 768 + 255) / 256, 256>>>(x, dA0, dA1, BROWS * 768);
    launch_hmma<2, true, 1>(dA0, dA1, ew0 + eoff[0], ew1 + eoff[0], eb[0],
                            nullptr, dB0, dB1, BROWS, 2048, 768);
    launch_hmma<2, true, 1>(dB0, dB1, ew0 + eoff[1], ew1 + eoff[1], eb[1],
                            nullptr, dA0, dA1, BROWS, 1024, 2048);
    launch_hmma<2, true, 1>(dA0, dA1, ew0 + eoff[2], ew1 + eoff[2], eb[2],
                            nullptr, dB0, dB1, BROWS, 512, 1024);
    launch_hmma<2, false, 0>(dB0, dB1, ew0 + eoff[3], ew1 + eoff[3], eb[3],
                             res, nullptr, nullptr, BROWS, 128, 512);

    // ---- residual quantization (speculative, with margin flags) ----
    k_rq_init<<<(BROWS * ZD + 255) / 256, 256>>>();
    dim3 rqg((BROWS + RQ_ROWS - 1) / RQ_ROWS, NUM_EXPERTS);
    for (int l = 0; l < NUM_LEVELS; l++)
        rq_level<<<rqg, 256, RQ_SMEM>>>(cb, out + IDX_OFF, l);

    // ---- exact batched repair of flagged rows ----
    k_compact <<<BROWS / 256, 256>>>();
    k_padcount<<<1, 1>>>();
    k_gather  <<<BROWS, 256>>>(x);
    launch_repair_sgemm<true >(gx,  ew[0], eb[0], rb0, 2048, 768);
    launch_repair_sgemm<true >(rb0, ew[1], eb[1], rb1, 1024, 2048);
    launch_repair_sgemm<true >(rb1, ew[2], eb[2], rb0, 512,  1024);
    launch_repair_sgemm<false>(rb0, ew[3], eb[3], rz,  128,  512);
    rq_redo<<<BROWS, 256>>>(labels, cb, out + IDX_OFF);

    k_loss_finish<<<1, 1024>>>(out + LOSS_OFF);

    // ---- x_q output + decoder input split (fused) ----
    k_xq_out<<<(BROWS * ZD + 255) / 256, 256>>>(xq, out + XQ_OFF, dA0, dA1);

    // ---- decoder (bf16x3 HMMA, STAGES=2 -> 2 CTAs/SM) ----
    launch_hmma<2, true, 1>(dA0, dA1, dw0 + doff[0], dw1 + doff[0], db[0],
                            nullptr, dB0, dB1, BROWS, 512, 128);
    launch_hmma<2, true, 1>(dB0, dB1, dw0 + doff[1], dw1 + doff[1], db[1],
                            nullptr, dA0, dA1, BROWS, 1024, 512);
    launch_hmma<2, true, 1>(dA0, dA1, dw0 + doff[2], dw1 + doff[2], db[2],
                            nullptr, dB0, dB1, BROWS, 2048, 1024);
    launch_hmma<2, false, 0>(dB0, dB1, dw0 + doff[3], dw1 + doff[3], db[3],
                             out + OUT_OFF, nullptr, nullptr, BROWS, 768, 2048);
}

// round 17
// speedup vs baseline: 4.8255x; 1.0817x over previous
#include <cuda_runtime.h>
#include <cuda_bf16.h>
#include <cstdint>

#define BROWS 32768
#define NUM_EXPERTS 10
#define NUM_LEVELS 4
#define CBK 256
#define ZD 128
#define BETA 0.001f
#define RQ_ROWS 32
#define TAU 1e-5f

#define OUT_OFF  0
#define LOSS_OFF (32768 * 768)
#define IDX_OFF  (LOSS_OFF + 1)
#define XQ_OFF   (IDX_OFF + 32768 * 4)

// ---------------------------------------------------------------------------
// Device scratch
// ---------------------------------------------------------------------------
__device__ float g_res [32768 * ZD];
__device__ float g_xq  [32768 * ZD];
__device__ float g_lossbuf[32768];
__device__ int   g_counts[NUM_EXPERTS];
__device__ int   g_cursor[NUM_EXPERTS];
__device__ int   g_offsets[NUM_EXPERTS + 1];
__device__ int   g_perm[32768];
__device__ int   g_rowflag[32768];
__device__ int   g_replist[32768];
__device__ int   g_nrep;
__device__ int   g_npad;

// repair batch buffers
__device__ float g_gx  [32768u * 768u];
__device__ float g_rb0 [32768u * 2048u];
__device__ float g_rb1 [32768u * 1024u];
__device__ float g_rz  [32768u * ZD];

// bf16 hi/lo activation ping-pong + split weights
__device__ __nv_bfloat16 g_dA0[32768u * 1024u];
__device__ __nv_bfloat16 g_dA1[32768u * 1024u];
__device__ __nv_bfloat16 g_dB0[32768u * 2048u];
__device__ __nv_bfloat16 g_dB1[32768u * 2048u];
#define W_TOTAL 4259840
__device__ __nv_bfloat16 g_dw0[W_TOTAL];
__device__ __nv_bfloat16 g_dw1[W_TOTAL];
__device__ __nv_bfloat16 g_ew0[W_TOTAL];
__device__ __nv_bfloat16 g_ew1[W_TOTAL];

// ---------------------------------------------------------------------------
// PTX helpers
// ---------------------------------------------------------------------------
__device__ __forceinline__ uint32_t smem_u32(const void* p) {
    uint32_t a;
    asm("{ .reg .u64 t; cvta.to.shared.u64 t, %1; cvt.u32.u64 %0, t; }"
        : "=r"(a) : "l"(p));
    return a;
}
__device__ __forceinline__ void cpa16(uint32_t dst, const void* src) {
    asm volatile("cp.async.cg.shared.global [%0], [%1], 16;" :: "r"(dst), "l"(src) : "memory");
}
#define CP_COMMIT() asm volatile("cp.async.commit_group;" ::: "memory")
#define CP_WAIT(n)  asm volatile("cp.async.wait_group %0;" :: "n"(n) : "memory")

#define LDSM4(r0, r1, r2, r3, addr) \
    asm volatile("ldmatrix.sync.aligned.m8n8.x4.shared.b16 {%0,%1,%2,%3}, [%4];" \
        : "=r"(r0), "=r"(r1), "=r"(r2), "=r"(r3) : "r"(addr))

#define MMA16816(acc, a, b0, b1) \
    asm volatile("mma.sync.aligned.m16n8k16.row.col.f32.bf16.bf16.f32 " \
        "{%0,%1,%2,%3}, {%4,%5,%6,%7}, {%8,%9}, {%0,%1,%2,%3};" \
        : "+f"((acc)[0]), "+f"((acc)[1]), "+f"((acc)[2]), "+f"((acc)[3]) \
        : "r"((a)[0]), "r"((a)[1]), "r"((a)[2]), "r"((a)[3]), "r"(b0), "r"(b1))

#define FMA2(d, a, b) \
    asm("fma.rn.f32x2 %0, %1, %2, %0;" : "+l"(d) : "l"(a), "l"(b))
#define PACK2(out, x) \
    asm("mov.b64 %0, {%1, %1};" : "=l"(out) : "f"(x))
#define UNPACK2(lo, hi, in) \
    asm("mov.b64 {%0, %1}, %2;" : "=f"(lo), "=f"(hi) : "l"(in))

// ---------------------------------------------------------------------------
// HMMA bf16x3 GEMM (validated; STAGES=2 -> 2 CTAs/SM).
// ---------------------------------------------------------------------------
#define TSTRIDE 40
#define SUBTILE (128 * TSTRIDE * 2)

template <int STAGES, bool RELU, int OMODE>
__global__ __launch_bounds__(256)
void hmma_gemm(const __nv_bfloat16* __restrict__ A0, const __nv_bfloat16* __restrict__ A1,
               const __nv_bfloat16* __restrict__ B0, const __nv_bfloat16* __restrict__ B1,
               const float* __restrict__ bias, float* __restrict__ Cf,
               __nv_bfloat16* __restrict__ C0, __nv_bfloat16* __restrict__ C1,
               int M, int N, int K)
{
    constexpr int STAGE = 4 * SUBTILE;
    extern __shared__ char smem[];
    const uint32_t sbase = smem_u32(smem);

    const int tid  = threadIdx.x;
    const int lane = tid & 31;
    const int wid  = tid >> 5;
    const int wm   = wid & 3;
    const int wn   = wid >> 2;
    const int m0   = blockIdx.y * 128;
    const int n0   = blockIdx.x * 128;
    const int nch  = K >> 5;

    float acc[2][8][4];
#pragma unroll
    for (int a = 0; a < 2; a++)
#pragma unroll
        for (int b = 0; b < 8; b++)
#pragma unroll
            for (int c = 0; c < 4; c++) acc[a][b][c] = 0.f;

    auto load_stage = [&](int stg, int k0) {
        const uint32_t sb_ = sbase + stg * STAGE;
#pragma unroll
        for (int ii = 0; ii < 2; ii++) {
            const int i = tid + ii * 256;
            const int r = i >> 2, c = i & 3;
            const uint32_t so = r * 80 + c * 16;
            const size_t ga = (size_t)(m0 + r) * K + k0 + c * 8;
            const size_t gb = (size_t)(n0 + r) * K + k0 + c * 8;
            cpa16(sb_ + so,               A0 + ga);
            cpa16(sb_ + SUBTILE + so,     A1 + ga);
            cpa16(sb_ + 2 * SUBTILE + so, B0 + gb);
            cpa16(sb_ + 3 * SUBTILE + so, B1 + gb);
        }
    };

#pragma unroll
    for (int s = 0; s < STAGES; s++) {
        if (s < nch) load_stage(s, s * 32);
        CP_COMMIT();
    }

    const int lrow = lane & 15;
    const int lsel = (lane >> 4) << 3;

    for (int ch = 0; ch < nch; ch++) {
        CP_WAIT(STAGES - 1);
        __syncthreads();
        const uint32_t sb = sbase + (ch % STAGES) * STAGE;
        const uint32_t Ahb = sb, Alb = sb + SUBTILE;
        const uint32_t Bhb = sb + 2 * SUBTILE, Blb = sb + 3 * SUBTILE;

#pragma unroll
        for (int kk = 0; kk < 32; kk += 16) {
            uint32_t ah[2][4], al[2][4];
#pragma unroll
            for (int mt = 0; mt < 2; mt++) {
                uint32_t off = ((wm * 32 + mt * 16 + lrow) * TSTRIDE + kk + lsel) * 2;
                LDSM4(ah[mt][0], ah[mt][1], ah[mt][2], ah[mt][3], Ahb + off);
                LDSM4(al[mt][0], al[mt][1], al[mt][2], al[mt][3], Alb + off);
            }
            uint32_t bh[8][2], bl[8][2];
#pragma unroll
            for (int g = 0; g < 4; g++) {
                uint32_t off = ((wn * 64 + g * 16 + lrow) * TSTRIDE + kk + lsel) * 2;
                uint32_t t0, t1, t2, t3;
                LDSM4(t0, t1, t2, t3, Bhb + off);
                bh[2*g][0] = t0;   bh[2*g][1] = t2;
                bh[2*g+1][0] = t1; bh[2*g+1][1] = t3;
                LDSM4(t0, t1, t2, t3, Blb + off);
                bl[2*g][0] = t0;   bl[2*g][1] = t2;
                bl[2*g+1][0] = t1; bl[2*g+1][1] = t3;
            }
#pragma unroll
            for (int mt = 0; mt < 2; mt++)
#pragma unroll
                for (int nt = 0; nt < 8; nt++) {
                    MMA16816(acc[mt][nt], ah[mt], bh[nt][0], bh[nt][1]);
                    MMA16816(acc[mt][nt], ah[mt], bl[nt][0], bl[nt][1]);
                    MMA16816(acc[mt][nt], al[mt], bh[nt][0], bh[nt][1]);
                }
        }
        __syncthreads();
        if (ch + STAGES < nch) load_stage(ch % STAGES, (ch + STAGES) * 32);
        CP_COMMIT();
    }

    const int gid = lane >> 2;
    const int tg  = lane & 3;
#pragma unroll
    for (int mt = 0; mt < 2; mt++) {
#pragma unroll
        for (int nt = 0; nt < 8; nt++) {
            const int col = n0 + wn * 64 + nt * 8 + tg * 2;
            const float2 bb = __ldg((const float2*)(bias + col));
#pragma unroll
            for (int h = 0; h < 2; h++) {
                const int row = m0 + wm * 32 + mt * 16 + gid + h * 8;
                float v0 = acc[mt][nt][2*h]   + bb.x;
                float v1 = acc[mt][nt][2*h+1] + bb.y;
                if (RELU) { v0 = fmaxf(v0, 0.f); v1 = fmaxf(v1, 0.f); }
                if (OMODE == 0) {
                    *(float2*)(Cf + (size_t)row * N + col) = make_float2(v0, v1);
                } else {
                    __nv_bfloat16 h0 = __float2bfloat16(v0);
                    __nv_bfloat16 h1 = __float2bfloat16(v1);
                    __nv_bfloat162 p0; p0.x = h0; p0.y = h1;
                    __nv_bfloat162 p1;
                    p1.x = __float2bfloat16(v0 - __bfloat162float(h0));
                    p1.y = __float2bfloat16(v1 - __bfloat162float(h1));
                    *(__nv_bfloat162*)(C0 + (size_t)row * N + col) = p0;
                    *(__nv_bfloat162*)(C1 + (size_t)row * N + col) = p1;
                }
            }
        }
    }
}

// ---------------------------------------------------------------------------
// Exact fp32 FFMA2 SGEMM (repair path; dynamic row-limit, graph-safe).
// ---------------------------------------------------------------------------
template <bool RELU>
__global__ __launch_bounds__(256, 2)
void sgemm_dyn(const float* __restrict__ A, const float* __restrict__ W,
               const float* __restrict__ bias, float* __restrict__ C,
               int M, int N, int K)
{
    if (blockIdx.y * 128 >= g_npad) return;

    __shared__ float As[2][16][128];
    __shared__ float Bs[3][16][128];

    const int t  = threadIdx.x;
    const int bm = blockIdx.y;
    const int bn = blockIdx.x;
    const int tx = t & 15;
    const int ty = t >> 4;

    const int ar0 = t >> 2;
    const int akq = (t & 3) * 4;
    const int bk0 = t >> 5;
    const int bcq = (t & 31) * 4;

    const float* Ag = A + (size_t)(bm * 128) * K;
    const float* Wg = W + bn * 128;

    const uint32_t bs_base0 = smem_u32(&Bs[0][bk0][bcq]);
    const uint32_t bs_base1 = smem_u32(&Bs[0][8 + bk0][bcq]);
    const uint32_t BS_STAGE = 16 * 128 * 4;

    unsigned long long acc2[8][4];
#pragma unroll
    for (int i = 0; i < 8; i++)
#pragma unroll
        for (int j = 0; j < 4; j++) acc2[i][j] = 0ull;

    const int nch = K >> 4;

    float4 pa0 = *(const float4*)(Ag + (size_t)ar0 * K + akq);
    float4 pa1 = *(const float4*)(Ag + (size_t)(64 + ar0) * K + akq);
    cpa16(bs_base0, Wg + (size_t)bk0 * N + bcq);
    cpa16(bs_base1, Wg + (size_t)(8 + bk0) * N + bcq);
    CP_COMMIT();
    if (nch > 1) {
        cpa16(bs_base0 + BS_STAGE, Wg + (size_t)(16 + bk0) * N + bcq);
        cpa16(bs_base1 + BS_STAGE, Wg + (size_t)(16 + 8 + bk0) * N + bcq);
    }
    CP_COMMIT();

    for (int ch = 0; ch < nch; ch++) {
        const int s  = ch & 1;
        const int bs = ch % 3;
        As[s][akq + 0][ar0] = pa0.x;
        As[s][akq + 1][ar0] = pa0.y;
        As[s][akq + 2][ar0] = pa0.z;
        As[s][akq + 3][ar0] = pa0.w;
        As[s][akq + 0][64 + ar0] = pa1.x;
        As[s][akq + 1][64 + ar0] = pa1.y;
        As[s][akq + 2][64 + ar0] = pa1.z;
        As[s][akq + 3][64 + ar0] = pa1.w;
        CP_WAIT(1);
        __syncthreads();

        if (ch + 2 < nch) {
            const int k0 = (ch + 2) << 4;
            const uint32_t dst = (uint32_t)(((ch + 2) % 3) * BS_STAGE);
            cpa16(bs_base0 + dst, Wg + (size_t)(k0 + bk0) * N + bcq);
            cpa16(bs_base1 + dst, Wg + (size_t)(k0 + 8 + bk0) * N + bcq);
        }
        CP_COMMIT();
        if (ch + 1 < nch) {
            const int k0 = (ch + 1) << 4;
            pa0 = *(const float4*)(Ag + (size_t)ar0 * K + k0 + akq);
            pa1 = *(const float4*)(Ag + (size_t)(64 + ar0) * K + k0 + akq);
        }

#pragma unroll
        for (int k = 0; k < 16; k++) {
            float a[8];
            *(float4*)&a[0] = *(const float4*)&As[s][k][ty * 8];
            *(float4*)&a[4] = *(const float4*)&As[s][k][ty * 8 + 4];
            const ulonglong2 b01 = *(const ulonglong2*)&Bs[bs][k][tx * 8];
            const ulonglong2 b23 = *(const ulonglong2*)&Bs[bs][k][tx * 8 + 4];
            unsigned long long bp[4] = {b01.x, b01.y, b23.x, b23.y};
            unsigned long long ap[8];
#pragma unroll
            for (int i = 0; i < 8; i++) PACK2(ap[i], a[i]);
#pragma unroll
            for (int i = 0; i < 8; i++)
#pragma unroll
                for (int j = 0; j < 4; j++)
                    FMA2(acc2[i][j], ap[i], bp[j]);
        }
    }

    const int crow0 = bm * 128 + ty * 8;
    const int ccol0 = bn * 128 + tx * 8;
    float bb[8];
#pragma unroll
    for (int j = 0; j < 8; j++) bb[j] = bias[ccol0 + j];

#pragma unroll
    for (int i = 0; i < 8; i++) {
        float v[8];
#pragma unroll
        for (int j = 0; j < 4; j++) {
            float lo, hi;
            UNPACK2(lo, hi, acc2[i][j]);
            float x0 = lo + bb[2 * j];
            float x1 = hi + bb[2 * j + 1];
            if (RELU) { x0 = fmaxf(x0, 0.f); x1 = fmaxf(x1, 0.f); }
            v[2 * j] = x0;
            v[2 * j + 1] = x1;
        }
        float* cp = C + (size_t)(crow0 + i) * N + ccol0;
        *(float4*)(cp)     = *(float4*)&v[0];
        *(float4*)(cp + 4) = *(float4*)&v[4];
    }
}

// ---------------------------------------------------------------------------
// Preprocessing
// ---------------------------------------------------------------------------
__global__ void k_wprep2(const float* __restrict__ W, __nv_bfloat16* __restrict__ T0,
                         __nv_bfloat16* __restrict__ T1, int K, int N)
{
    __shared__ float t[32][33];
    int n = blockIdx.x * 32 + threadIdx.x;
    int k = blockIdx.y * 32 + threadIdx.y;
    t[threadIdx.y][threadIdx.x] = W[(size_t)k * N + n];
    __syncthreads();
    int nn = blockIdx.x * 32 + threadIdx.y;
    int kk = blockIdx.y * 32 + threadIdx.x;
    float v = t[threadIdx.x][threadIdx.y];
    __nv_bfloat16 h = __float2bfloat16(v);
    T0[(size_t)nn * K + kk] = h;
    T1[(size_t)nn * K + kk] = __float2bfloat16(v - __bfloat162float(h));
}

__global__ void k_split(const float* __restrict__ src, __nv_bfloat16* __restrict__ o0,
                        __nv_bfloat16* __restrict__ o1, int n)
{
    int i = blockIdx.x * 256 + threadIdx.x;
    if (i < n) {
        float v = src[i];
        __nv_bfloat16 h = __float2bfloat16(v);
        o0[i] = h;
        o1[i] = __float2bfloat16(v - __bfloat162float(h));
    }
}

__global__ void k_xq_out(const float* __restrict__ xq, float* __restrict__ dst,
                         __nv_bfloat16* __restrict__ o0, __nv_bfloat16* __restrict__ o1)
{
    int i = blockIdx.x * 256 + threadIdx.x;
    if (i < BROWS * ZD) {
        float v = xq[i];
        dst[i] = v;
        __nv_bfloat16 h = __float2bfloat16(v);
        o0[i] = h;
        o1[i] = __float2bfloat16(v - __bfloat162float(h));
    }
}

// ---------------------------------------------------------------------------
// Expert counting-sort + init
// ---------------------------------------------------------------------------
__global__ void k_zero_counts() {
    int t = threadIdx.x;
    if (t < NUM_EXPERTS) { g_counts[t] = 0; g_cursor[t] = 0; }
    if (t == 0) { g_nrep = 0; g_npad = 0; }
}
__global__ void k_hist(const int* __restrict__ labels) {
    int i = blockIdx.x * blockDim.x + threadIdx.x;
    if (i < BROWS) atomicAdd(&g_counts[labels[i]], 1);
}
__global__ void k_scan() {
    if (threadIdx.x == 0) {
        int s = 0;
        for (int e = 0; e < NUM_EXPERTS; e++) { g_offsets[e] = s; s += g_counts[e]; }
        g_offsets[NUM_EXPERTS] = s;
    }
}
__global__ void k_scatter(const int* __restrict__ labels) {
    int i = blockIdx.x * blockDim.x + threadIdx.x;
    if (i < BROWS) {
        int e = labels[i];
        int p = atomicAdd(&g_cursor[e], 1);
        g_perm[g_offsets[e] + p] = i;
    }
}

// ---------------------------------------------------------------------------
// Fused residual quantization: all 4 levels in one kernel. res/xq/loss/flag
// stay resident in smem across levels; codebook streamed per level (same L2
// traffic as before). Per-row math & order identical to the validated R16
// kernels (same scores, same argmin, same update & xq += q accumulation).
// ---------------------------------------------------------------------------
__global__ __launch_bounds__(256)
void rq_fused(const float* __restrict__ cb, float* __restrict__ idx_out)
{
    extern __shared__ float c_sh[];        // 256 * 129 floats (codebook)
    __shared__ float res_all[RQ_ROWS][ZD];
    __shared__ float xq_all [RQ_ROWS][ZD];
    __shared__ float loss_all[RQ_ROWS];
    __shared__ int   flag_all[RQ_ROWS];
    __shared__ float cn_sh[CBK];
    __shared__ float s_ws[8];
    __shared__ int   s_wi[8];
    __shared__ float s_w2[8];
    __shared__ float s_red[4];
    __shared__ int   s_kmin;

    const int e     = blockIdx.y;
    const int start = g_offsets[e];
    const int end   = g_offsets[e + 1];
    const int rbase = start + blockIdx.x * RQ_ROWS;
    if (rbase >= end) return;

    const int t = threadIdx.x;
    const int lane = t & 31;
    const int warp = t >> 5;
    const float INF = __int_as_float(0x7f800000);
    const int nrows = min(RQ_ROWS, end - rbase);

    // load residual rows; init xq/loss/flag
    for (int i = warp; i < nrows; i += 8) {
        const int row = g_perm[rbase + i];
        for (int j = lane; j < ZD; j += 32) {
            res_all[i][j] = g_res[(size_t)row * ZD + j];
            xq_all[i][j] = 0.f;
        }
    }
    if (t < RQ_ROWS) { loss_all[t] = 0.f; flag_all[t] = 0; }
    __syncthreads();

    for (int level = 0; level < NUM_LEVELS; level++) {
        // stream this level's codebook into smem (padded stride 129)
        const float* cbl = cb + ((size_t)level * NUM_EXPERTS + e) * CBK * ZD;
        for (int i = t; i < (CBK * ZD) / 4; i += 256) {
            float4 v = ((const float4*)cbl)[i];
            int k = i >> 5;
            int j = (i & 31) << 2;
            float* d = &c_sh[k * 129 + j];
            d[0] = v.x; d[1] = v.y; d[2] = v.z; d[3] = v.w;
        }
        __syncthreads();
        {
            const float* cr = &c_sh[t * 129];
            float s = 0.f;
#pragma unroll 8
            for (int j = 0; j < ZD; j++) s += cr[j] * cr[j];
            cn_sh[t] = s;
        }
        __syncthreads();

        for (int i = 0; i < nrows; i++) {
            float dot = 0.f;
            const float* cr = &c_sh[t * 129];
            const float* rs = res_all[i];
#pragma unroll 8
            for (int j = 0; j < ZD; j++) dot += cr[j] * rs[j];
            float s1 = cn_sh[t] - 2.f * dot;
            int   i1 = t;
            float s2 = INF;

#pragma unroll
            for (int o = 16; o > 0; o >>= 1) {
                float t1 = __shfl_down_sync(0xffffffffu, s1, o);
                int   j1 = __shfl_down_sync(0xffffffffu, i1, o);
                float t2 = __shfl_down_sync(0xffffffffu, s2, o);
                if (t1 < s1 || (t1 == s1 && j1 < i1)) {
                    s2 = fminf(s1, t2);
                    s1 = t1; i1 = j1;
                } else {
                    s2 = fminf(s2, t1);
                }
            }
            if (lane == 0) { s_ws[warp] = s1; s_wi[warp] = i1; s_w2[warp] = s2; }
            __syncthreads();
            if (t == 0) {
                float bs = s_ws[0]; int bi = s_wi[0]; float b2 = s_w2[0];
#pragma unroll
                for (int w = 1; w < 8; w++) {
                    float u1 = s_ws[w]; int u = s_wi[w]; float u2 = s_w2[w];
                    if (u1 < bs || (u1 == bs && u < bi)) {
                        b2 = fminf(bs, u2);
                        bs = u1; bi = u;
                    } else {
                        b2 = fminf(b2, u1);
                    }
                }
                s_kmin = bi;
                if (b2 - bs < TAU * (1.0f + fabsf(bs))) flag_all[i] = 1;
            }
            __syncthreads();
            const int kmin = s_kmin;

            float sq = 0.f;
            if (t < ZD) {
                float q  = c_sh[kmin * 129 + t];
                float nr = res_all[i][t] - q;
                res_all[i][t] = nr;
                xq_all[i][t] += q;
                sq = nr * nr;
            }
#pragma unroll
            for (int o = 16; o > 0; o >>= 1) sq += __shfl_down_sync(0xffffffffu, sq, o);
            if (t < ZD && lane == 0) s_red[warp] = sq;
            __syncthreads();
            if (t == 0) {
                loss_all[i] += s_red[0] + s_red[1] + s_red[2] + s_red[3];
                const int row = g_perm[rbase + i];
                idx_out[row * 4 + level] = (float)kmin;
            }
            __syncthreads();
        }
        __syncthreads();   // all rows done before codebook overwrite
    }

    // write back xq / loss / flag
    for (int i = warp; i < nrows; i += 8) {
        const int row = g_perm[rbase + i];
        for (int j = lane; j < ZD; j += 32)
            g_xq[(size_t)row * ZD + j] = xq_all[i][j];
        if (lane == 0) {
            g_lossbuf[row] = loss_all[i];
            g_rowflag[row] = flag_all[i];
        }
    }
}

__global__ void k_compact() {
    int i = blockIdx.x * blockDim.x + threadIdx.x;
    if (i < BROWS && g_rowflag[i]) {
        int p = atomicAdd(&g_nrep, 1);
        g_replist[p] = i;
    }
}
__global__ void k_padcount() {
    if (threadIdx.x == 0) g_npad = ((g_nrep + 127) / 128) * 128;
}

// gather flagged x rows (grid-stride over compact batch)
__global__ void k_gather(const float* __restrict__ x)
{
    const int t = threadIdx.x;
    for (int fi = blockIdx.x; fi < g_npad; fi += gridDim.x) {
        float* dst = g_gx + (size_t)fi * 768;
        if (fi < g_nrep) {
            const float* src = x + (size_t)g_replist[fi] * 768;
            for (int j = t; j < 768; j += 256) dst[j] = src[j];
        } else {
            for (int j = t; j < 768; j += 256) dst[j] = 0.f;
        }
    }
}

// ---------------------------------------------------------------------------
// Exact RQ redo for flagged rows (identical expressions to rq path).
// ---------------------------------------------------------------------------
__global__ __launch_bounds__(256)
void rq_redo(const int* __restrict__ labels, const float* __restrict__ cb,
             float* __restrict__ idx_out)
{
    __shared__ float res_s[ZD];
    __shared__ float xq_s[ZD];
    __shared__ float s_ws[8];
    __shared__ int   s_wi[8];
    __shared__ float s_red[4];
    __shared__ int   s_kmin;
    __shared__ float s_loss;

    const int t = threadIdx.x;
    const int lane = t & 31;
    const int warp = t >> 5;

    for (int fi = blockIdx.x; fi < g_nrep; fi += gridDim.x) {
        const int row = g_replist[fi];

        if (t < ZD) { res_s[t] = g_rz[(size_t)fi * ZD + t]; xq_s[t] = 0.f; }
        if (t == 0) s_loss = 0.f;
        __syncthreads();

        const int e = labels[row];
        for (int l = 0; l < NUM_LEVELS; l++) {
            const float* cbl = cb + ((size_t)l * NUM_EXPERTS + e) * CBK * ZD;
            const float* cr = cbl + (size_t)t * ZD;
            float cn = 0.f, dot = 0.f;
#pragma unroll 8
            for (int j = 0; j < ZD; j++) cn  += cr[j] * cr[j];
#pragma unroll 8
            for (int j = 0; j < ZD; j++) dot += cr[j] * res_s[j];
            float sc = cn - 2.f * dot;
            int   ix = t;
#pragma unroll
            for (int o = 16; o > 0; o >>= 1) {
                float sc2 = __shfl_down_sync(0xffffffffu, sc, o);
                int   ix2 = __shfl_down_sync(0xffffffffu, ix, o);
                if (sc2 < sc || (sc2 == sc && ix2 < ix)) { sc = sc2; ix = ix2; }
            }
            if (lane == 0) { s_ws[warp] = sc; s_wi[warp] = ix; }
            __syncthreads();
            if (t == 0) {
                float bs = s_ws[0]; int bi = s_wi[0];
#pragma unroll
                for (int w = 1; w < 8; w++) {
                    float u = s_ws[w]; int ui = s_wi[w];
                    if (u < bs || (u == bs && ui < bi)) { bs = u; bi = ui; }
                }
                s_kmin = bi;
            }
            __syncthreads();
            const int kmin = s_kmin;

            float sq = 0.f;
            if (t < ZD) {
                float q  = cbl[(size_t)kmin * ZD + t];
                float nr = res_s[t] - q;
                res_s[t] = nr;
                xq_s[t] += q;
                sq = nr * nr;
            }
            __syncthreads();
#pragma unroll
            for (int o = 16; o > 0; o >>= 1) sq += __shfl_down_sync(0xffffffffu, sq, o);
            if (t < ZD && lane == 0) s_red[warp] = sq;
            __syncthreads();
            if (t == 0) {
                s_loss += s_red[0] + s_red[1] + s_red[2] + s_red[3];
                idx_out[row * 4 + l] = (float)kmin;
            }
            __syncthreads();
        }
        if (t < ZD) g_xq[(size_t)row * ZD + t] = xq_s[t];
        if (t == 0) g_lossbuf[row] = s_loss;
        __syncthreads();
    }
}

__global__ void k_loss_finish(float* __restrict__ loss_out) {
    __shared__ float sm[1024];
    float s = 0.f;
    for (int i = threadIdx.x; i < BROWS; i += 1024) s += g_lossbuf[i];
    sm[threadIdx.x] = s;
    __syncthreads();
    for (int k = 512; k > 0; k >>= 1) {
        if (threadIdx.x < k) sm[threadIdx.x] += sm[threadIdx.x + k];
        __syncthreads();
    }
    if (threadIdx.x == 0)
        loss_out[0] = sm[0] * (1.f + BETA) / ((float)BROWS * (float)ZD);
}

// ---------------------------------------------------------------------------
// Host launch
// ---------------------------------------------------------------------------
template <int STAGES, bool RELU, int OMODE>
static void launch_hmma(const __nv_bfloat16* a0, const __nv_bfloat16* a1,
                        const __nv_bfloat16* b0, const __nv_bfloat16* b1,
                        const float* bias, float* cf,
                        __nv_bfloat16* c0, __nv_bfloat16* c1,
                        int M, int N, int K)
{
    constexpr int SMEMB = STAGES * 4 * SUBTILE;
    cudaFuncSetAttribute(hmma_gemm<STAGES, RELU, OMODE>,
                         cudaFuncAttributeMaxDynamicSharedMemorySize, SMEMB);
    dim3 g(N / 128, M / 128);
    hmma_gemm<STAGES, RELU, OMODE><<<g, 256, SMEMB>>>(
        a0, a1, b0, b1, bias, cf, c0, c1, M, N, K);
}

template <bool RELU>
static void launch_repair_sgemm(const float* A, const float* W, const float* b,
                                float* C, int N, int K)
{
    dim3 grid(N / 128, BROWS / 128);   // blocks early-exit on g_npad
    sgemm_dyn<RELU><<<grid, 256>>>(A, W, b, C, BROWS, N, K);
}

extern "C" void kernel_launch(void* const* d_in, const int* in_sizes, int n_in,
                              void* d_out, int out_size)
{
    const float* x      = (const float*)d_in[0];
    const int*   labels = (const int*)  d_in[1];
    const float* ew[4]  = {(const float*)d_in[2], (const float*)d_in[4],
                           (const float*)d_in[6], (const float*)d_in[8]};
    const float* eb[4]  = {(const float*)d_in[3], (const float*)d_in[5],
                           (const float*)d_in[7], (const float*)d_in[9]};
    const float* dw[4]  = {(const float*)d_in[10], (const float*)d_in[12],
                           (const float*)d_in[14], (const float*)d_in[16]};
    const float* db[4]  = {(const float*)d_in[11], (const float*)d_in[13],
                           (const float*)d_in[15], (const float*)d_in[17]};
    const float* cb     = (const float*)d_in[18];
    float* out = (float*)d_out;

    float *res, *xq, *gx, *rb0, *rb1, *rz;
    __nv_bfloat16 *dA0, *dA1, *dB0, *dB1, *dw0, *dw1, *ew0, *ew1;
    cudaGetSymbolAddress((void**)&res,  g_res);
    cudaGetSymbolAddress((void**)&xq,   g_xq);
    cudaGetSymbolAddress((void**)&gx,   g_gx);
    cudaGetSymbolAddress((void**)&rb0,  g_rb0);
    cudaGetSymbolAddress((void**)&rb1,  g_rb1);
    cudaGetSymbolAddress((void**)&rz,   g_rz);
    cudaGetSymbolAddress((void**)&dA0,  g_dA0);
    cudaGetSymbolAddress((void**)&dA1,  g_dA1);
    cudaGetSymbolAddress((void**)&dB0,  g_dB0);
    cudaGetSymbolAddress((void**)&dB1,  g_dB1);
    cudaGetSymbolAddress((void**)&dw0,  g_dw0);
    cudaGetSymbolAddress((void**)&dw1,  g_dw1);
    cudaGetSymbolAddress((void**)&ew0,  g_ew0);
    cudaGetSymbolAddress((void**)&ew1,  g_ew1);

    static const int RQ_SMEM = CBK * 129 * sizeof(float);
    cudaFuncSetAttribute(rq_fused, cudaFuncAttributeMaxDynamicSharedMemorySize, RQ_SMEM);

    const int eLN[4] = {2048, 1024, 512, 128};
    const int eLK[4] = {768, 2048, 1024, 512};
    const int dLN[4] = {512, 1024, 2048, 768};
    const int dLK[4] = {128, 512, 1024, 2048};
    size_t eoff[4], doff[4];
    {
        size_t o = 0;
        for (int i = 0; i < 4; i++) { eoff[i] = o; o += (size_t)eLN[i] * eLK[i]; }
        o = 0;
        for (int i = 0; i < 4; i++) { doff[i] = o; o += (size_t)dLN[i] * dLK[i]; }
    }

    // ---- preprocess weights ----
    for (int i = 0; i < 4; i++) {
        dim3 b(32, 32);
        dim3 ge(eLN[i] / 32, eLK[i] / 32);
        k_wprep2<<<ge, b>>>(ew[i], ew0 + eoff[i], ew1 + eoff[i], eLK[i], eLN[i]);
        dim3 gd(dLN[i] / 32, dLK[i] / 32);
        k_wprep2<<<gd, b>>>(dw[i], dw0 + doff[i], dw1 + doff[i], dLK[i], dLN[i]);
    }

    // ---- expert grouping ----
    k_zero_counts<<<1, 32>>>();
    k_hist   <<<BROWS / 256, 256>>>(labels);
    k_scan   <<<1, 1>>>();
    k_scatter<<<BROWS / 256, 256>>>(labels);

    // ---- encoder (bf16x3 tensor cores; flips caught by margin+repair) ----
    k_split<<<(BROWS * 768 + 255) / 256, 256>>>(x, dA0, dA1, BROWS * 768);
    launch_hmma<2, true, 1>(dA0, dA1, ew0 + eoff[0], ew1 + eoff[0], eb[0],
                            nullptr, dB0, dB1, BROWS, 2048, 768);
    launch_hmma<2, true, 1>(dB0, dB1, ew0 + eoff[1], ew1 + eoff[1], eb[1],
                            nullptr, dA0, dA1, BROWS, 1024, 2048);
    launch_hmma<2, true, 1>(dA0, dA1, ew0 + eoff[2], ew1 + eoff[2], eb[2],
                            nullptr, dB0, dB1, BROWS, 512, 1024);
    launch_hmma<2, false, 0>(dB0, dB1, ew0 + eoff[3], ew1 + eoff[3], eb[3],
                             res, nullptr, nullptr, BROWS, 128, 512);

    // ---- residual quantization (fused 4 levels, speculative + flags) ----
    dim3 rqg((BROWS + RQ_ROWS - 1) / RQ_ROWS, NUM_EXPERTS);
    rq_fused<<<rqg, 256, RQ_SMEM>>>(cb, out + IDX_OFF);

    // ---- exact batched repair of flagged rows ----
    k_compact <<<BROWS / 256, 256>>>();
    k_padcount<<<1, 1>>>();
    k_gather  <<<2048, 256>>>(x);
    launch_repair_sgemm<true >(gx,  ew[0], eb[0], rb0, 2048, 768);
    launch_repair_sgemm<true >(rb0, ew[1], eb[1], rb1, 1024, 2048);
    launch_repair_sgemm<true >(rb1, ew[2], eb[2], rb0, 512,  1024);
    launch_repair_sgemm<false>(rb0, ew[3], eb[3], rz,  128,  512);
    rq_redo<<<2048, 256>>>(labels, cb, out + IDX_OFF);

    k_loss_finish<<<1, 1024>>>(out + LOSS_OFF);

    // ---- x_q output + decoder input split (fused) ----
    k_xq_out<<<(BROWS * ZD + 255) / 256, 256>>>(xq, out + XQ_OFF, dA0, dA1);

    // ---- decoder (bf16x3 HMMA, STAGES=2 -> 2 CTAs/SM) ----
    launch_hmma<2, true, 1>(dA0, dA1, dw0 + doff[0], dw1 + doff[0], db[0],
                            nullptr, dB0, dB1, BROWS, 512, 128);
    launch_hmma<2, true, 1>(dB0, dB1, dw0 + doff[1], dw1 + doff[1], db[1],
                            nullptr, dA0, dA1, BROWS, 1024, 512);
    launch_hmma<2, true, 1>(dA0, dA1, dw0 + doff[2], dw1 + doff[2], db[2],
                            nullptr, dB0, dB1, BROWS, 2048, 1024);
    launch_hmma<2, false, 0>(dB0, dB1, dw0 + doff[3], dw1 + doff[3], db[3],
                             out + OUT_OFF, nullptr, nullptr, BROWS, 768, 2048);
}